// round 2
// baseline (speedup 1.0000x reference)
#include <cuda_runtime.h>
#include <cuda_bf16.h>

#define S_LEN   2048
#define BATCH   2
#define NH      16
#define NKV     4
#define DH      64
#define DMODEL  1024
#define WINDOW  256
#define NGLOB   4

// Scratch buffers (allocation-free rule: __device__ globals)
__device__ float g_q[BATCH * S_LEN * NH * DH];     // [tok,16,64]
__device__ float g_k[BATCH * S_LEN * NKV * DH];    // [tok,4,64]
__device__ float g_v[BATCH * S_LEN * NKV * DH];    // [tok,4,64]
__device__ float g_ctx[BATCH * S_LEN * NH * DH];   // [tok,1024]

// ---------------- GEMM: C[M,N] = A[M,K] * B[K,N], all row-major ----------------
#define BM 128
#define BN 128
#define BK 16

__device__ __forceinline__ void gemm_body(const float* __restrict__ A,
                                          const float* __restrict__ B,
                                          float* __restrict__ C,
                                          int N, int K, int bx, int by,
                                          float (*As)[BM], float (*Bs)[BN]) {
    const int tid  = threadIdx.x;
    const int tCol = tid & 15;        // 16 thread-cols
    const int tRow = tid >> 4;        // 16 thread-rows
    const int aRow = tid >> 2;        // 0..63
    const int aCol = (tid & 3) << 2;  // 0,4,8,12
    const int bRow = tid >> 5;        // 0..7
    const int bCol = (tid & 31) << 2; // 0..124

    A += by * BM * K;
    B += bx * BN;
    C += by * BM * N + bx * BN;

    float acc[8][8];
#pragma unroll
    for (int i = 0; i < 8; ++i)
#pragma unroll
        for (int j = 0; j < 8; ++j) acc[i][j] = 0.0f;

    for (int k0 = 0; k0 < K; k0 += BK) {
        float4 a0 = *(const float4*)(A + aRow * K + k0 + aCol);
        float4 a1 = *(const float4*)(A + (aRow + 64) * K + k0 + aCol);
        As[aCol + 0][aRow] = a0.x;
        As[aCol + 1][aRow] = a0.y;
        As[aCol + 2][aRow] = a0.z;
        As[aCol + 3][aRow] = a0.w;
        As[aCol + 0][aRow + 64] = a1.x;
        As[aCol + 1][aRow + 64] = a1.y;
        As[aCol + 2][aRow + 64] = a1.z;
        As[aCol + 3][aRow + 64] = a1.w;
        *(float4*)&Bs[bRow][bCol]     = *(const float4*)(B + (k0 + bRow) * N + bCol);
        *(float4*)&Bs[bRow + 8][bCol] = *(const float4*)(B + (k0 + bRow + 8) * N + bCol);
        __syncthreads();
#pragma unroll
        for (int kk = 0; kk < BK; ++kk) {
            float ar[8], br[8];
            *(float4*)&ar[0] = *(const float4*)&As[kk][(tRow << 3) + 0];
            *(float4*)&ar[4] = *(const float4*)&As[kk][(tRow << 3) + 4];
            *(float4*)&br[0] = *(const float4*)&Bs[kk][(tCol << 3) + 0];
            *(float4*)&br[4] = *(const float4*)&Bs[kk][(tCol << 3) + 4];
#pragma unroll
            for (int i = 0; i < 8; ++i)
#pragma unroll
                for (int j = 0; j < 8; ++j)
                    acc[i][j] = fmaf(ar[i], br[j], acc[i][j]);
        }
        __syncthreads();
    }
#pragma unroll
    for (int i = 0; i < 8; ++i) {
        float4 c0, c1;
        c0.x = acc[i][0]; c0.y = acc[i][1]; c0.z = acc[i][2]; c0.w = acc[i][3];
        c1.x = acc[i][4]; c1.y = acc[i][5]; c1.z = acc[i][6]; c1.w = acc[i][7];
        float* crow = C + ((tRow << 3) + i) * N + (tCol << 3);
        *(float4*)(crow + 0) = c0;
        *(float4*)(crow + 4) = c1;
    }
}

// Fused QKV projection: grid.x 0..7 -> Q (N=1024), 8..9 -> K (N=256), 10..11 -> V
__global__ __launch_bounds__(256) void gemm_qkv_kernel(const float* __restrict__ x,
                                                       const float* __restrict__ Wq,
                                                       const float* __restrict__ Wk,
                                                       const float* __restrict__ Wv) {
    __shared__ float As[BK][BM];
    __shared__ float Bs[BK][BN];
    const int bx = blockIdx.x, by = blockIdx.y;
    if (bx < 8)       gemm_body(x, Wq, g_q, 1024, 1024, bx,      by, As, Bs);
    else if (bx < 10) gemm_body(x, Wk, g_k, 256,  1024, bx - 8,  by, As, Bs);
    else              gemm_body(x, Wv, g_v, 256,  1024, bx - 10, by, As, Bs);
}

__global__ __launch_bounds__(256) void gemm_out_kernel(const float* __restrict__ Wo,
                                                       float* __restrict__ out) {
    __shared__ float As[BK][BM];
    __shared__ float Bs[BK][BN];
    gemm_body(g_ctx, Wo, out, 1024, 1024, blockIdx.x, blockIdx.y, As, Bs);
}

// ---------------- L2 normalize + RoPE (warp per token-head) ----------------
__global__ void normrope_kernel(const float* __restrict__ cosv,
                                const float* __restrict__ sinv) {
    const int gw   = (blockIdx.x * blockDim.x + threadIdx.x) >> 5;
    const int lane = threadIdx.x & 31;
    const int NQ   = BATCH * S_LEN * NH;
    const int NTOT = NQ + BATCH * S_LEN * NKV;
    if (gw >= NTOT) return;
    float* base;
    int tok;
    if (gw < NQ) { base = g_q + gw * DH; tok = gw / NH; }
    else         { int g2 = gw - NQ; base = g_k + g2 * DH; tok = g2 / NKV; }
    const int s = tok & (S_LEN - 1);

    float x1 = base[lane];
    float x2 = base[lane + 32];
    float ss = x1 * x1 + x2 * x2;
#pragma unroll
    for (int o = 16; o; o >>= 1) ss += __shfl_xor_sync(0xffffffffu, ss, o);
    const float inv = 1.0f / (sqrtf(ss) + 1e-8f);
    x1 *= inv; x2 *= inv;
    const float c  = cosv[s * 32 + lane];
    const float sn = sinv[s * 32 + lane];
    base[lane]      = x1 * c - x2 * sn;
    base[lane + 32] = x1 * sn + x2 * c;
}

// ---------------- Attention (lane = query; 64-key SMEM chunks) ----------------
__global__ __launch_bounds__(128) void attn_kernel() {
    __shared__ float Ks[64 * 64];
    __shared__ float Vs[64 * 64];
    const int tid  = threadIdx.x;
    const int lane = tid & 31;
    const int w    = tid >> 5;
    const int bh   = blockIdx.y;
    const int b    = bh >> 4;
    const int h    = bh & 15;
    const int kh   = h >> 2;
    const int qb   = blockIdx.x << 7;        // 128-query tile base
    const int sq   = qb + (w << 5) + lane;   // this lane's query

    // load q vector (pre-normalized + roped)
    float q[64];
    {
        const float4* qp = (const float4*)(g_q + ((b * S_LEN + sq) * NH + h) * DH);
#pragma unroll
        for (int i = 0; i < 16; ++i) {
            float4 t = qp[i];
            q[4 * i + 0] = t.x; q[4 * i + 1] = t.y;
            q[4 * i + 2] = t.z; q[4 * i + 3] = t.w;
        }
    }
    float acc[64];
#pragma unroll
    for (int i = 0; i < 64; ++i) acc[i] = 0.0f;
    float l = 0.0f;

    const int lo_chunk = (qb > (WINDOW - 1)) ? ((qb - (WINDOW - 1)) >> 6) : 0;
    const int hi_chunk = (qb + 127) >> 6;
    const int wqmax    = qb + (w << 5) + 31;

    for (int c = 0; c <= hi_chunk; ++c) {
        if (c > 0 && c < lo_chunk) continue;   // uniform across block
        {
            const float* Kbase = g_k + ((b * S_LEN + (c << 6)) * NKV + kh) * DH;
            const float* Vbase = g_v + ((b * S_LEN + (c << 6)) * NKV + kh) * DH;
            float4* k4 = (float4*)Ks;
            float4* v4 = (float4*)Vs;
#pragma unroll
            for (int r = 0; r < 8; ++r) {
                int f = (r << 7) + tid;          // 0..1023 float4s
                int row = f >> 4, c4 = f & 15;
                k4[f] = ((const float4*)(Kbase + row * (NKV * DH)))[c4];
                v4[f] = ((const float4*)(Vbase + row * (NKV * DH)))[c4];
            }
        }
        __syncthreads();
        const int jmax = min(63, wqmax - (c << 6));
        for (int j = 0; j <= jmax; ++j) {
            const int key = (c << 6) + j;
            const float4* kr = (const float4*)(Ks + (j << 6));
            float s0 = 0.f, s1 = 0.f, s2 = 0.f, s3 = 0.f;
#pragma unroll
            for (int dd = 0; dd < 4; ++dd) {
                float4 ka = kr[4 * dd + 0];
                float4 kb = kr[4 * dd + 1];
                float4 kc = kr[4 * dd + 2];
                float4 kd = kr[4 * dd + 3];
                s0 = fmaf(q[16 * dd +  0], ka.x, s0); s1 = fmaf(q[16 * dd +  1], ka.y, s1);
                s2 = fmaf(q[16 * dd +  2], ka.z, s2); s3 = fmaf(q[16 * dd +  3], ka.w, s3);
                s0 = fmaf(q[16 * dd +  4], kb.x, s0); s1 = fmaf(q[16 * dd +  5], kb.y, s1);
                s2 = fmaf(q[16 * dd +  6], kb.z, s2); s3 = fmaf(q[16 * dd +  7], kb.w, s3);
                s0 = fmaf(q[16 * dd +  8], kc.x, s0); s1 = fmaf(q[16 * dd +  9], kc.y, s1);
                s2 = fmaf(q[16 * dd + 10], kc.z, s2); s3 = fmaf(q[16 * dd + 11], kc.w, s3);
                s0 = fmaf(q[16 * dd + 12], kd.x, s0); s1 = fmaf(q[16 * dd + 13], kd.y, s1);
                s2 = fmaf(q[16 * dd + 14], kd.z, s2); s3 = fmaf(q[16 * dd + 15], kd.w, s3);
            }
            const float sdot = (s0 + s1) + (s2 + s3);
            // softcap: 15*tanh(s/15) = s - s^3/675 + O(s^5), |s|<=0.125 -> err < 1e-10
            const float sc  = sdot * 0.125f;
            const float cap = sc - sc * sc * sc * (1.0f / 675.0f);
            // causal applies to BOTH window and global keys (reference ANDs input causal mask)
            const bool valid = (key <= sq) && ((key > sq - WINDOW) || (key < NGLOB));
            const float p = valid ? __expf(cap) : 0.0f;
            l += p;
            const float4* vr = (const float4*)(Vs + (j << 6));
#pragma unroll
            for (int dd = 0; dd < 16; ++dd) {
                float4 vv = vr[dd];
                acc[4 * dd + 0] = fmaf(p, vv.x, acc[4 * dd + 0]);
                acc[4 * dd + 1] = fmaf(p, vv.y, acc[4 * dd + 1]);
                acc[4 * dd + 2] = fmaf(p, vv.z, acc[4 * dd + 2]);
                acc[4 * dd + 3] = fmaf(p, vv.w, acc[4 * dd + 3]);
            }
        }
        __syncthreads();
    }

    const float invl = 1.0f / l;   // query attends to itself -> l > 0
    float* Op = g_ctx + ((b * S_LEN + sq) * NH + h) * DH;
#pragma unroll
    for (int dd = 0; dd < 16; ++dd) {
        float4 o;
        o.x = acc[4 * dd + 0] * invl;
        o.y = acc[4 * dd + 1] * invl;
        o.z = acc[4 * dd + 2] * invl;
        o.w = acc[4 * dd + 3] * invl;
        *(float4*)(Op + 4 * dd) = o;
    }
}

// ---------------- launch ----------------
extern "C" void kernel_launch(void* const* d_in, const int* in_sizes, int n_in,
                              void* d_out, int out_size) {
    const float* x    = (const float*)d_in[0];
    const float* cosv = (const float*)d_in[1];
    const float* sinv = (const float*)d_in[2];
    // d_in[3] = mask (bool) — causal+window+global mask recomputed analytically
    const float* Wq   = (const float*)d_in[4];
    const float* Wk   = (const float*)d_in[5];
    const float* Wv   = (const float*)d_in[6];
    const float* Wo   = (const float*)d_in[7];
    float* out = (float*)d_out;

    gemm_qkv_kernel<<<dim3(12, 32), 256>>>(x, Wq, Wk, Wv);

    const int nwarps  = BATCH * S_LEN * (NH + NKV);      // 81920
    const int nthread = nwarps * 32;
    normrope_kernel<<<(nthread + 255) / 256, 256>>>(cosv, sinv);

    attn_kernel<<<dim3(S_LEN / 128, BATCH * NH), 128>>>();

    gemm_out_kernel<<<dim3(DMODEL / BN, (BATCH * S_LEN) / BM), 256>>>(Wo, out);
}

// round 7
// speedup vs baseline: 1.4192x; 1.4192x over previous
#include <cuda_runtime.h>
#include <cuda_bf16.h>

#define S_LEN   2048
#define BATCH   2
#define NH      16
#define NKV     4
#define DH      64
#define DMODEL  1024
#define WINDOW  256
#define NGLOB   4

// Scratch buffers (allocation-free rule: __device__ globals)
__device__ float g_q[BATCH * S_LEN * NH * DH];     // [tok,16,64]
__device__ float g_k[BATCH * S_LEN * NKV * DH];    // [tok,4,64]
__device__ float g_v[BATCH * S_LEN * NKV * DH];    // [tok,4,64]
__device__ float g_ctx[BATCH * S_LEN * NH * DH];   // [tok,1024]
// Transposed weights (B^T, row-major [N][K]) for mma.sync row.col
__device__ float g_wqt[1024 * 1024];
__device__ float g_wkt[256 * 1024];
__device__ float g_wvt[256 * 1024];
__device__ float g_wot[1024 * 1024];

// ---------------- weight transpose: g_w?t[C][R] = in[R][C]^T ----------------
// NOTE: output selected by `sel` IN DEVICE CODE — __device__ globals must not
// be passed as kernel arguments from host (host sees the shadow symbol; on
// GB300/ATS the write lands in host RAM and the GPU copy stays zero).
__global__ __launch_bounds__(256) void tr_kernel(const float* __restrict__ in,
                                                 int sel, int R, int C) {
    float* __restrict__ out = (sel == 0) ? g_wqt
                            : (sel == 1) ? g_wkt
                            : (sel == 2) ? g_wvt : g_wot;
    __shared__ float t[32][33];
    const int bx = blockIdx.x * 32, by = blockIdx.y * 32;
    const int x = bx + threadIdx.x;
#pragma unroll
    for (int i = threadIdx.y; i < 32; i += 8)
        t[i][threadIdx.x] = in[(by + i) * C + x];
    __syncthreads();
    const int xo = by + threadIdx.x;
#pragma unroll
    for (int i = threadIdx.y; i < 32; i += 8)
        out[(bx + i) * R + xo] = t[threadIdx.x][i];
}

// ---------------- bf16 tensor-core GEMM with hi/lo compensation ----------------
// C = A * Bt^T, fp32 in/out.  a = a_hi + a_lo (bf16 split), product via
// Ahi*Bhi + Ahi*Blo + Alo*Bhi (fp32 accum) -> elementwise rel err ~4e-6.
// Block 128x128, k-chunk 32 (two m16n8k16 steps). 8 warps, warp tile 64x32.
// SMEM: packed bf16x2 (low half = even k), uint32 rows of stride 20
// (conflict-free fragment fetches: (20*grp+qd) mod 32 all distinct).
#define BKC   32
#define SSTR  20

__device__ __forceinline__ void split2(float x, float y, unsigned& hi, unsigned& lo) {
    __nv_bfloat16 hx = __float2bfloat16(x);
    __nv_bfloat16 hy = __float2bfloat16(y);
    __nv_bfloat16 lx = __float2bfloat16(x - __bfloat162float(hx));
    __nv_bfloat16 ly = __float2bfloat16(y - __bfloat162float(hy));
    hi = ((unsigned)__bfloat16_as_ushort(hy) << 16) | __bfloat16_as_ushort(hx);
    lo = ((unsigned)__bfloat16_as_ushort(ly) << 16) | __bfloat16_as_ushort(lx);
}

__device__ __forceinline__ void mma_bf16(float* d, unsigned a0, unsigned a1,
                                         unsigned a2, unsigned a3,
                                         unsigned b0, unsigned b1) {
    asm volatile(
        "mma.sync.aligned.m16n8k16.row.col.f32.bf16.bf16.f32 "
        "{%0,%1,%2,%3}, {%4,%5,%6,%7}, {%8,%9}, {%0,%1,%2,%3};"
        : "+f"(d[0]), "+f"(d[1]), "+f"(d[2]), "+f"(d[3])
        : "r"(a0), "r"(a1), "r"(a2), "r"(a3), "r"(b0), "r"(b1));
}

__device__ __forceinline__ void gemm_tc_body(const float* __restrict__ A,
                                             const float* __restrict__ Bt,
                                             float* __restrict__ C,
                                             int N, int K, int bx, int by,
                                             unsigned* Ahi, unsigned* Alo,
                                             unsigned* Bhi, unsigned* Blo) {
    const int tid  = threadIdx.x;
    const int lane = tid & 31;
    const int warp = tid >> 5;
    const int grp  = lane >> 2;          // 0..7
    const int qd   = lane & 3;           // 0..3
    const int wm    = (warp >> 2) << 6;  // 0 or 64
    const int wncol = (warp & 3) << 5;   // 0,32,64,96

    A  += (size_t)by * 128 * K;
    Bt += (size_t)bx * 128 * K;
    C  += (size_t)by * 128 * N + bx * 128;

    float acc[4][4][4];
#pragma unroll
    for (int i = 0; i < 4; ++i)
#pragma unroll
        for (int j = 0; j < 4; ++j)
#pragma unroll
            for (int r = 0; r < 4; ++r) acc[i][j][r] = 0.0f;

    const int ldRow = tid >> 3;          // 0..31
    const int ldT   = tid & 7;           // 0..7 -> k = 4*ldT..+3

    for (int k0 = 0; k0 < K; k0 += BKC) {
#pragma unroll
        for (int i = 0; i < 4; ++i) {
            const int row = i * 32 + ldRow;
            float4 va = *(const float4*)(A  + (size_t)row * K + k0 + ldT * 4);
            float4 vb = *(const float4*)(Bt + (size_t)row * K + k0 + ldT * 4);
            unsigned h0, l0, h1, l1;
            split2(va.x, va.y, h0, l0);
            split2(va.z, va.w, h1, l1);
            Ahi[row * SSTR + ldT * 2]     = h0;
            Ahi[row * SSTR + ldT * 2 + 1] = h1;
            Alo[row * SSTR + ldT * 2]     = l0;
            Alo[row * SSTR + ldT * 2 + 1] = l1;
            split2(vb.x, vb.y, h0, l0);
            split2(vb.z, vb.w, h1, l1);
            Bhi[row * SSTR + ldT * 2]     = h0;
            Bhi[row * SSTR + ldT * 2 + 1] = h1;
            Blo[row * SSTR + ldT * 2]     = l0;
            Blo[row * SSTR + ldT * 2 + 1] = l1;
        }
        __syncthreads();

#pragma unroll
        for (int h = 0; h < 2; ++h) {      // two k16 steps per chunk
            unsigned ah[4][4], al[4][4], bh[4][2], bl[4][2];
#pragma unroll
            for (int mt = 0; mt < 4; ++mt) {
                const int r0 = (wm + mt * 16 + grp) * SSTR + h * 8 + qd;
                const int r1 = r0 + 8 * SSTR;
                ah[mt][0] = Ahi[r0];     ah[mt][1] = Ahi[r1];
                ah[mt][2] = Ahi[r0 + 4]; ah[mt][3] = Ahi[r1 + 4];
                al[mt][0] = Alo[r0];     al[mt][1] = Alo[r1];
                al[mt][2] = Alo[r0 + 4]; al[mt][3] = Alo[r1 + 4];
            }
#pragma unroll
            for (int nt = 0; nt < 4; ++nt) {
                const int n0 = (wncol + nt * 8 + grp) * SSTR + h * 8 + qd;
                bh[nt][0] = Bhi[n0]; bh[nt][1] = Bhi[n0 + 4];
                bl[nt][0] = Blo[n0]; bl[nt][1] = Blo[n0 + 4];
            }
#pragma unroll
            for (int mt = 0; mt < 4; ++mt)
#pragma unroll
                for (int nt = 0; nt < 4; ++nt) {
                    mma_bf16(acc[mt][nt], ah[mt][0], ah[mt][1], ah[mt][2], ah[mt][3],
                             bh[nt][0], bh[nt][1]);
                    mma_bf16(acc[mt][nt], ah[mt][0], ah[mt][1], ah[mt][2], ah[mt][3],
                             bl[nt][0], bl[nt][1]);
                    mma_bf16(acc[mt][nt], al[mt][0], al[mt][1], al[mt][2], al[mt][3],
                             bh[nt][0], bh[nt][1]);
                }
        }
        __syncthreads();
    }

#pragma unroll
    for (int mt = 0; mt < 4; ++mt)
#pragma unroll
        for (int nt = 0; nt < 4; ++nt) {
            const int row = wm + mt * 16 + grp;
            const int col = wncol + nt * 8 + qd * 2;
            float2 lo; lo.x = acc[mt][nt][0]; lo.y = acc[mt][nt][1];
            float2 hi; hi.x = acc[mt][nt][2]; hi.y = acc[mt][nt][3];
            *(float2*)(C + (size_t)row * N + col)       = lo;
            *(float2*)(C + (size_t)(row + 8) * N + col) = hi;
        }
}

// Fused QKV projection: grid.x 0..7 -> Q, 8..9 -> K, 10..11 -> V
__global__ __launch_bounds__(256) void gemm_qkv_kernel(const float* __restrict__ x) {
    __shared__ unsigned Ahi[128 * SSTR], Alo[128 * SSTR];
    __shared__ unsigned Bhi[128 * SSTR], Blo[128 * SSTR];
    const int bx = blockIdx.x, by = blockIdx.y;
    if (bx < 8)       gemm_tc_body(x, g_wqt, g_q, 1024, 1024, bx,      by, Ahi, Alo, Bhi, Blo);
    else if (bx < 10) gemm_tc_body(x, g_wkt, g_k, 256,  1024, bx - 8,  by, Ahi, Alo, Bhi, Blo);
    else              gemm_tc_body(x, g_wvt, g_v, 256,  1024, bx - 10, by, Ahi, Alo, Bhi, Blo);
}

__global__ __launch_bounds__(256) void gemm_out_kernel(float* __restrict__ out) {
    __shared__ unsigned Ahi[128 * SSTR], Alo[128 * SSTR];
    __shared__ unsigned Bhi[128 * SSTR], Blo[128 * SSTR];
    gemm_tc_body(g_ctx, g_wot, out, 1024, 1024, blockIdx.x, blockIdx.y, Ahi, Alo, Bhi, Blo);
}

// ---------------- L2 normalize + RoPE (warp per token-head) ----------------
__global__ void normrope_kernel(const float* __restrict__ cosv,
                                const float* __restrict__ sinv) {
    const int gw   = (blockIdx.x * blockDim.x + threadIdx.x) >> 5;
    const int lane = threadIdx.x & 31;
    const int NQ   = BATCH * S_LEN * NH;
    const int NTOT = NQ + BATCH * S_LEN * NKV;
    if (gw >= NTOT) return;
    float* base;
    int tok;
    if (gw < NQ) { base = g_q + gw * DH; tok = gw / NH; }
    else         { int g2 = gw - NQ; base = g_k + g2 * DH; tok = g2 / NKV; }
    const int s = tok & (S_LEN - 1);

    float x1 = base[lane];
    float x2 = base[lane + 32];
    float ss = x1 * x1 + x2 * x2;
#pragma unroll
    for (int o = 16; o; o >>= 1) ss += __shfl_xor_sync(0xffffffffu, ss, o);
    const float inv = 1.0f / (sqrtf(ss) + 1e-8f);
    x1 *= inv; x2 *= inv;
    const float c  = cosv[s * 32 + lane];
    const float sn = sinv[s * 32 + lane];
    base[lane]      = x1 * c - x2 * sn;
    base[lane + 32] = x1 * sn + x2 * c;
}

// ---------------- Attention (lane = query; 64-key SMEM chunks) ----------------
__global__ __launch_bounds__(128) void attn_kernel() {
    __shared__ float Ks[64 * 64];
    __shared__ float Vs[64 * 64];
    const int tid  = threadIdx.x;
    const int lane = tid & 31;
    const int w    = tid >> 5;
    const int bh   = blockIdx.y;
    const int b    = bh >> 4;
    const int h    = bh & 15;
    const int kh   = h >> 2;
    const int qb   = blockIdx.x << 7;        // 128-query tile base
    const int sq   = qb + (w << 5) + lane;   // this lane's query

    float q[64];
    {
        const float4* qp = (const float4*)(g_q + ((b * S_LEN + sq) * NH + h) * DH);
#pragma unroll
        for (int i = 0; i < 16; ++i) {
            float4 t = qp[i];
            q[4 * i + 0] = t.x; q[4 * i + 1] = t.y;
            q[4 * i + 2] = t.z; q[4 * i + 3] = t.w;
        }
    }
    float acc[64];
#pragma unroll
    for (int i = 0; i < 64; ++i) acc[i] = 0.0f;
    float l = 0.0f;

    const int lo_chunk = (qb > (WINDOW - 1)) ? ((qb - (WINDOW - 1)) >> 6) : 0;
    const int hi_chunk = (qb + 127) >> 6;
    const int wqmax    = qb + (w << 5) + 31;

    for (int c = 0; c <= hi_chunk; ++c) {
        if (c > 0 && c < lo_chunk) continue;   // uniform across block
        {
            const float* Kbase = g_k + ((b * S_LEN + (c << 6)) * NKV + kh) * DH;
            const float* Vbase = g_v + ((b * S_LEN + (c << 6)) * NKV + kh) * DH;
            float4* k4 = (float4*)Ks;
            float4* v4 = (float4*)Vs;
#pragma unroll
            for (int r = 0; r < 8; ++r) {
                int f = (r << 7) + tid;          // 0..1023 float4s
                int row = f >> 4, c4 = f & 15;
                k4[f] = ((const float4*)(Kbase + row * (NKV * DH)))[c4];
                v4[f] = ((const float4*)(Vbase + row * (NKV * DH)))[c4];
            }
        }
        __syncthreads();
        const int jmax = min(63, wqmax - (c << 6));
        for (int j = 0; j <= jmax; ++j) {
            const int key = (c << 6) + j;
            const float4* kr = (const float4*)(Ks + (j << 6));
            float s0 = 0.f, s1 = 0.f, s2 = 0.f, s3 = 0.f;
#pragma unroll
            for (int dd = 0; dd < 4; ++dd) {
                float4 ka = kr[4 * dd + 0];
                float4 kb = kr[4 * dd + 1];
                float4 kc = kr[4 * dd + 2];
                float4 kd = kr[4 * dd + 3];
                s0 = fmaf(q[16 * dd +  0], ka.x, s0); s1 = fmaf(q[16 * dd +  1], ka.y, s1);
                s2 = fmaf(q[16 * dd +  2], ka.z, s2); s3 = fmaf(q[16 * dd +  3], ka.w, s3);
                s0 = fmaf(q[16 * dd +  4], kb.x, s0); s1 = fmaf(q[16 * dd +  5], kb.y, s1);
                s2 = fmaf(q[16 * dd +  6], kb.z, s2); s3 = fmaf(q[16 * dd +  7], kb.w, s3);
                s0 = fmaf(q[16 * dd +  8], kc.x, s0); s1 = fmaf(q[16 * dd +  9], kc.y, s1);
                s2 = fmaf(q[16 * dd + 10], kc.z, s2); s3 = fmaf(q[16 * dd + 11], kc.w, s3);
                s0 = fmaf(q[16 * dd + 12], kd.x, s0); s1 = fmaf(q[16 * dd + 13], kd.y, s1);
                s2 = fmaf(q[16 * dd + 14], kd.z, s2); s3 = fmaf(q[16 * dd + 15], kd.w, s3);
            }
            const float sdot = (s0 + s1) + (s2 + s3);
            // softcap: 15*tanh(s/15) = s - s^3/675 + O(s^5), |s|<=0.125 -> err < 1e-10
            const float sc  = sdot * 0.125f;
            const float cap = sc - sc * sc * sc * (1.0f / 675.0f);
            // causal applies to BOTH window and global keys
            const bool valid = (key <= sq) && ((key > sq - WINDOW) || (key < NGLOB));
            const float p = valid ? __expf(cap) : 0.0f;
            l += p;
            const float4* vr = (const float4*)(Vs + (j << 6));
#pragma unroll
            for (int dd = 0; dd < 16; ++dd) {
                float4 vv = vr[dd];
                acc[4 * dd + 0] = fmaf(p, vv.x, acc[4 * dd + 0]);
                acc[4 * dd + 1] = fmaf(p, vv.y, acc[4 * dd + 1]);
                acc[4 * dd + 2] = fmaf(p, vv.z, acc[4 * dd + 2]);
                acc[4 * dd + 3] = fmaf(p, vv.w, acc[4 * dd + 3]);
            }
        }
        __syncthreads();
    }

    const float invl = 1.0f / l;
    float* Op = g_ctx + ((b * S_LEN + sq) * NH + h) * DH;
#pragma unroll
    for (int dd = 0; dd < 16; ++dd) {
        float4 o;
        o.x = acc[4 * dd + 0] * invl;
        o.y = acc[4 * dd + 1] * invl;
        o.z = acc[4 * dd + 2] * invl;
        o.w = acc[4 * dd + 3] * invl;
        *(float4*)(Op + 4 * dd) = o;
    }
}

// ---------------- launch ----------------
extern "C" void kernel_launch(void* const* d_in, const int* in_sizes, int n_in,
                              void* d_out, int out_size) {
    const float* x    = (const float*)d_in[0];
    const float* cosv = (const float*)d_in[1];
    const float* sinv = (const float*)d_in[2];
    // d_in[3] = mask (bool) — recomputed analytically
    const float* Wq   = (const float*)d_in[4];
    const float* Wk   = (const float*)d_in[5];
    const float* Wv   = (const float*)d_in[6];
    const float* Wo   = (const float*)d_in[7];
    float* out = (float*)d_out;

    // transpose weights to [N][K]; output buffer chosen by selector IN DEVICE CODE
    tr_kernel<<<dim3(32, 32), dim3(32, 8)>>>(Wq, 0, 1024, 1024);
    tr_kernel<<<dim3(8,  32), dim3(32, 8)>>>(Wk, 1, 1024, 256);
    tr_kernel<<<dim3(8,  32), dim3(32, 8)>>>(Wv, 2, 1024, 256);
    tr_kernel<<<dim3(32, 32), dim3(32, 8)>>>(Wo, 3, 1024, 1024);

    gemm_qkv_kernel<<<dim3(12, 32), 256>>>(x);

    const int nwarps  = BATCH * S_LEN * (NH + NKV);      // 81920
    const int nthread = nwarps * 32;
    normrope_kernel<<<(nthread + 255) / 256, 256>>>(cosv, sinv);

    attn_kernel<<<dim3(S_LEN / 128, BATCH * NH), 128>>>();

    gemm_out_kernel<<<dim3(DMODEL / 128, (BATCH * S_LEN) / 128), 256>>>(out);
}

// round 8
// speedup vs baseline: 2.1536x; 1.5175x over previous
#include <cuda_runtime.h>
#include <cuda_bf16.h>

#define S_LEN   2048
#define BATCH   2
#define NH      16
#define NKV     4
#define DH      64
#define DMODEL  1024
#define WINDOW  256
#define NGLOB   4

// Scratch buffers (allocation-free rule: __device__ globals)
__device__ float g_q[BATCH * S_LEN * NH * DH];        // [tok,16,64]
__device__ float g_k[BATCH * S_LEN * NKV * DH];       // [tok,4,64]
__device__ float g_vt[NKV * DH * BATCH * S_LEN];      // TRANSPOSED V: [kvh*64+dh][tok]
__device__ float g_ctx[BATCH * S_LEN * NH * DH];      // [tok,1024]
// Transposed weights (B^T, row-major [N][K]) for mma.sync row.col
__device__ float g_wqt[1024 * 1024];
__device__ float g_wkt[256 * 1024];
__device__ float g_wvt[256 * 1024];
__device__ float g_wot[1024 * 1024];

// ---------------- weight transpose: g_w?t[C][R] = in[R][C]^T ----------------
// NOTE: output selected by `sel` IN DEVICE CODE — __device__ globals must not
// be passed as kernel arguments from host (host sees the shadow symbol).
__global__ __launch_bounds__(256) void tr_kernel(const float* __restrict__ in,
                                                 int sel, int R, int C) {
    float* __restrict__ out = (sel == 0) ? g_wqt
                            : (sel == 1) ? g_wkt
                            : (sel == 2) ? g_wvt : g_wot;
    __shared__ float t[32][33];
    const int bx = blockIdx.x * 32, by = blockIdx.y * 32;
    const int x = bx + threadIdx.x;
#pragma unroll
    for (int i = threadIdx.y; i < 32; i += 8)
        t[i][threadIdx.x] = in[(by + i) * C + x];
    __syncthreads();
    const int xo = by + threadIdx.x;
#pragma unroll
    for (int i = threadIdx.y; i < 32; i += 8)
        out[(bx + i) * R + xo] = t[threadIdx.x][i];
}

// ---------------- bf16 tensor-core GEMM with hi/lo compensation ----------------
#define BKC   32
#define SSTR  20

__device__ __forceinline__ void split2(float x, float y, unsigned& hi, unsigned& lo) {
    __nv_bfloat16 hx = __float2bfloat16(x);
    __nv_bfloat16 hy = __float2bfloat16(y);
    __nv_bfloat16 lx = __float2bfloat16(x - __bfloat162float(hx));
    __nv_bfloat16 ly = __float2bfloat16(y - __bfloat162float(hy));
    hi = ((unsigned)__bfloat16_as_ushort(hy) << 16) | __bfloat16_as_ushort(hx);
    lo = ((unsigned)__bfloat16_as_ushort(ly) << 16) | __bfloat16_as_ushort(lx);
}

__device__ __forceinline__ void mma_bf16(float* d, unsigned a0, unsigned a1,
                                         unsigned a2, unsigned a3,
                                         unsigned b0, unsigned b1) {
    asm volatile(
        "mma.sync.aligned.m16n8k16.row.col.f32.bf16.bf16.f32 "
        "{%0,%1,%2,%3}, {%4,%5,%6,%7}, {%8,%9}, {%0,%1,%2,%3};"
        : "+f"(d[0]), "+f"(d[1]), "+f"(d[2]), "+f"(d[3])
        : "r"(a0), "r"(a1), "r"(a2), "r"(a3), "r"(b0), "r"(b1));
}

__device__ __forceinline__ void gemm_tc_body(const float* __restrict__ A,
                                             const float* __restrict__ Bt,
                                             float* __restrict__ C,
                                             int N, int K, int bx, int by, int vt,
                                             unsigned* Ahi, unsigned* Alo,
                                             unsigned* Bhi, unsigned* Blo) {
    const int tid  = threadIdx.x;
    const int lane = tid & 31;
    const int warp = tid >> 5;
    const int grp  = lane >> 2;          // 0..7
    const int qd   = lane & 3;           // 0..3
    const int wm    = (warp >> 2) << 6;  // 0 or 64
    const int wncol = (warp & 3) << 5;   // 0,32,64,96

    A  += (size_t)by * 128 * K;
    Bt += (size_t)bx * 128 * K;

    float acc[4][4][4];
#pragma unroll
    for (int i = 0; i < 4; ++i)
#pragma unroll
        for (int j = 0; j < 4; ++j)
#pragma unroll
            for (int r = 0; r < 4; ++r) acc[i][j][r] = 0.0f;

    const int ldRow = tid >> 3;          // 0..31
    const int ldT   = tid & 7;           // 0..7 -> k = 4*ldT..+3

    for (int k0 = 0; k0 < K; k0 += BKC) {
#pragma unroll
        for (int i = 0; i < 4; ++i) {
            const int row = i * 32 + ldRow;
            float4 va = *(const float4*)(A  + (size_t)row * K + k0 + ldT * 4);
            float4 vb = *(const float4*)(Bt + (size_t)row * K + k0 + ldT * 4);
            unsigned h0, l0, h1, l1;
            split2(va.x, va.y, h0, l0);
            split2(va.z, va.w, h1, l1);
            Ahi[row * SSTR + ldT * 2]     = h0;
            Ahi[row * SSTR + ldT * 2 + 1] = h1;
            Alo[row * SSTR + ldT * 2]     = l0;
            Alo[row * SSTR + ldT * 2 + 1] = l1;
            split2(vb.x, vb.y, h0, l0);
            split2(vb.z, vb.w, h1, l1);
            Bhi[row * SSTR + ldT * 2]     = h0;
            Bhi[row * SSTR + ldT * 2 + 1] = h1;
            Blo[row * SSTR + ldT * 2]     = l0;
            Blo[row * SSTR + ldT * 2 + 1] = l1;
        }
        __syncthreads();

#pragma unroll
        for (int h = 0; h < 2; ++h) {      // two k16 steps per chunk
            unsigned ah[4][4], al[4][4], bh[4][2], bl[4][2];
#pragma unroll
            for (int mt = 0; mt < 4; ++mt) {
                const int r0 = (wm + mt * 16 + grp) * SSTR + h * 8 + qd;
                const int r1 = r0 + 8 * SSTR;
                ah[mt][0] = Ahi[r0];     ah[mt][1] = Ahi[r1];
                ah[mt][2] = Ahi[r0 + 4]; ah[mt][3] = Ahi[r1 + 4];
                al[mt][0] = Alo[r0];     al[mt][1] = Alo[r1];
                al[mt][2] = Alo[r0 + 4]; al[mt][3] = Alo[r1 + 4];
            }
#pragma unroll
            for (int nt = 0; nt < 4; ++nt) {
                const int n0 = (wncol + nt * 8 + grp) * SSTR + h * 8 + qd;
                bh[nt][0] = Bhi[n0]; bh[nt][1] = Bhi[n0 + 4];
                bl[nt][0] = Blo[n0]; bl[nt][1] = Blo[n0 + 4];
            }
#pragma unroll
            for (int mt = 0; mt < 4; ++mt)
#pragma unroll
                for (int nt = 0; nt < 4; ++nt) {
                    mma_bf16(acc[mt][nt], ah[mt][0], ah[mt][1], ah[mt][2], ah[mt][3],
                             bh[nt][0], bh[nt][1]);
                    mma_bf16(acc[mt][nt], ah[mt][0], ah[mt][1], ah[mt][2], ah[mt][3],
                             bl[nt][0], bl[nt][1]);
                    mma_bf16(acc[mt][nt], al[mt][0], al[mt][1], al[mt][2], al[mt][3],
                             bh[nt][0], bh[nt][1]);
                }
        }
        __syncthreads();
    }

    if (vt) {
        // transposed store into g_vt[col][token]
#pragma unroll
        for (int mt = 0; mt < 4; ++mt)
#pragma unroll
            for (int nt = 0; nt < 4; ++nt) {
                const int row_g = by * 128 + wm + mt * 16 + grp;
                const int col_g = bx * 128 + wncol + nt * 8 + qd * 2;
                g_vt[(size_t)col_g       * (BATCH * S_LEN) + row_g]     = acc[mt][nt][0];
                g_vt[(size_t)(col_g + 1) * (BATCH * S_LEN) + row_g]     = acc[mt][nt][1];
                g_vt[(size_t)col_g       * (BATCH * S_LEN) + row_g + 8] = acc[mt][nt][2];
                g_vt[(size_t)(col_g + 1) * (BATCH * S_LEN) + row_g + 8] = acc[mt][nt][3];
            }
    } else {
        C += (size_t)by * 128 * N + bx * 128;
#pragma unroll
        for (int mt = 0; mt < 4; ++mt)
#pragma unroll
            for (int nt = 0; nt < 4; ++nt) {
                const int row = wm + mt * 16 + grp;
                const int col = wncol + nt * 8 + qd * 2;
                float2 lo; lo.x = acc[mt][nt][0]; lo.y = acc[mt][nt][1];
                float2 hi; hi.x = acc[mt][nt][2]; hi.y = acc[mt][nt][3];
                *(float2*)(C + (size_t)row * N + col)       = lo;
                *(float2*)(C + (size_t)(row + 8) * N + col) = hi;
            }
    }
}

// Fused QKV projection: grid.x 0..7 -> Q, 8..9 -> K, 10..11 -> V (transposed out)
__global__ __launch_bounds__(256) void gemm_qkv_kernel(const float* __restrict__ x) {
    __shared__ unsigned Ahi[128 * SSTR], Alo[128 * SSTR];
    __shared__ unsigned Bhi[128 * SSTR], Blo[128 * SSTR];
    const int bx = blockIdx.x, by = blockIdx.y;
    if (bx < 8)       gemm_tc_body(x, g_wqt, g_q, 1024, 1024, bx,      by, 0, Ahi, Alo, Bhi, Blo);
    else if (bx < 10) gemm_tc_body(x, g_wkt, g_k, 256,  1024, bx - 8,  by, 0, Ahi, Alo, Bhi, Blo);
    else              gemm_tc_body(x, g_wvt, g_vt, 256, 1024, bx - 10, by, 1, Ahi, Alo, Bhi, Blo);
}

__global__ __launch_bounds__(256) void gemm_out_kernel(float* __restrict__ out) {
    __shared__ unsigned Ahi[128 * SSTR], Alo[128 * SSTR];
    __shared__ unsigned Bhi[128 * SSTR], Blo[128 * SSTR];
    gemm_tc_body(g_ctx, g_wot, out, 1024, 1024, blockIdx.x, blockIdx.y, 0, Ahi, Alo, Bhi, Blo);
}

// ---------------- L2 normalize + RoPE (warp per token-head; Q and K only) ------
__global__ void normrope_kernel(const float* __restrict__ cosv,
                                const float* __restrict__ sinv) {
    const int gw   = (blockIdx.x * blockDim.x + threadIdx.x) >> 5;
    const int lane = threadIdx.x & 31;
    const int NQ   = BATCH * S_LEN * NH;
    const int NTOT = NQ + BATCH * S_LEN * NKV;
    if (gw >= NTOT) return;
    float* base;
    int tok;
    if (gw < NQ) { base = g_q + gw * DH; tok = gw / NH; }
    else         { int g2 = gw - NQ; base = g_k + g2 * DH; tok = g2 / NKV; }
    const int s = tok & (S_LEN - 1);

    float x1 = base[lane];
    float x2 = base[lane + 32];
    float ss = x1 * x1 + x2 * x2;
#pragma unroll
    for (int o = 16; o; o >>= 1) ss += __shfl_xor_sync(0xffffffffu, ss, o);
    const float inv = 1.0f / (sqrtf(ss) + 1e-8f);
    x1 *= inv; x2 *= inv;
    const float c  = cosv[s * 32 + lane];
    const float sn = sinv[s * 32 + lane];
    base[lane]      = x1 * c - x2 * sn;
    base[lane + 32] = x1 * sn + x2 * c;
}

// ---------------- Tensor-core attention ----------------
// Block: 64-query tile (4 warps x m16) for one (b, head). Keys in 64-chunks.
// S = Q K^T via hi/lo bf16 mma (3 passes); softcap/mask/exp in C-fragments;
// P hi/lo re-split; PV reuses S C-fragments as A-fragments (FA2 identity).
// K staged [key][dh-pairs] stride 36 (conflict-free fragment fetch);
// V read from g_vt (pre-transposed) and staged [dh][key-pairs] stride 36.
#define KSTR 36

__global__ __launch_bounds__(128, 2) void attn_tc_kernel() {
    __shared__ unsigned Khi[64 * KSTR], Klo[64 * KSTR];
    __shared__ unsigned Vthi[64 * KSTR], Vtlo[64 * KSTR];
    const int tid  = threadIdx.x;
    const int lane = tid & 31;
    const int w    = tid >> 5;
    const int g    = lane >> 2;
    const int qd   = lane & 3;
    const int bh   = blockIdx.y;
    const int b    = bh >> 4;
    const int h    = bh & 15;
    const int kh   = h >> 2;
    const int qb   = blockIdx.x << 6;       // 64-query tile base
    const int qrow = qb + (w << 4) + g;     // rows qrow and qrow+8

    // Q A-fragments (hi/lo) for 4 k-steps over dh
    unsigned qhf[4][4], qlf[4][4];
    {
        const float* Qb = g_q + ((size_t)(b * S_LEN + qb + (w << 4)) * NH + h) * DH;
        // token stride = NH*DH = 1024 floats
#pragma unroll
        for (int s = 0; s < 4; ++s) {
            float2 f0 = *(const float2*)(Qb + g * 1024 + s * 16 + 2 * qd);
            float2 f1 = *(const float2*)(Qb + (g + 8) * 1024 + s * 16 + 2 * qd);
            float2 f2 = *(const float2*)(Qb + g * 1024 + s * 16 + 8 + 2 * qd);
            float2 f3 = *(const float2*)(Qb + (g + 8) * 1024 + s * 16 + 8 + 2 * qd);
            split2(f0.x, f0.y, qhf[s][0], qlf[s][0]);
            split2(f1.x, f1.y, qhf[s][1], qlf[s][1]);
            split2(f2.x, f2.y, qhf[s][2], qlf[s][2]);
            split2(f3.x, f3.y, qhf[s][3], qlf[s][3]);
        }
    }

    float oacc[8][4];
#pragma unroll
    for (int i = 0; i < 8; ++i)
#pragma unroll
        for (int j = 0; j < 4; ++j) oacc[i][j] = 0.0f;
    float lsum0 = 0.0f, lsum1 = 0.0f;

    const int lo_chunk = (qb > (WINDOW - 1)) ? ((qb - (WINDOW - 1)) >> 6) : 0;
    const int hi_chunk = qb >> 6;

    for (int c = 0; c <= hi_chunk; ++c) {
        if (c > 0 && c < lo_chunk) continue;   // uniform across block
        // stage K chunk [key][dh] and V chunk [dh][key] as hi/lo bf16 pairs
        {
            const float* Kb = g_k + ((size_t)(b * S_LEN + (c << 6)) * NKV + kh) * DH;
#pragma unroll
            for (int r = 0; r < 8; ++r) {
                const int idx = (r << 7) + tid;
                const int row = idx >> 4, c4 = idx & 15;
                float4 v = *(const float4*)(Kb + (size_t)row * (NKV * DH) + c4 * 4);
                unsigned h0, l0, h1, l1;
                split2(v.x, v.y, h0, l0);
                split2(v.z, v.w, h1, l1);
                Khi[row * KSTR + c4 * 2]     = h0;
                Khi[row * KSTR + c4 * 2 + 1] = h1;
                Klo[row * KSTR + c4 * 2]     = l0;
                Klo[row * KSTR + c4 * 2 + 1] = l1;
            }
            const float* Vb = g_vt + (size_t)(kh * DH) * (BATCH * S_LEN)
                            + b * S_LEN + (c << 6);
#pragma unroll
            for (int r = 0; r < 8; ++r) {
                const int idx = (r << 7) + tid;
                const int row = idx >> 4, c4 = idx & 15;     // row = dh
                float4 v = *(const float4*)(Vb + (size_t)row * (BATCH * S_LEN) + c4 * 4);
                unsigned h0, l0, h1, l1;
                split2(v.x, v.y, h0, l0);
                split2(v.z, v.w, h1, l1);
                Vthi[row * KSTR + c4 * 2]     = h0;
                Vthi[row * KSTR + c4 * 2 + 1] = h1;
                Vtlo[row * KSTR + c4 * 2]     = l0;
                Vtlo[row * KSTR + c4 * 2 + 1] = l1;
            }
        }
        __syncthreads();

        // S = Q K^T  (warp: 16 q-rows x 64 keys)
        float sacc[8][4];
#pragma unroll
        for (int i = 0; i < 8; ++i)
#pragma unroll
            for (int j = 0; j < 4; ++j) sacc[i][j] = 0.0f;
#pragma unroll
        for (int s = 0; s < 4; ++s) {
#pragma unroll
            for (int nt = 0; nt < 8; ++nt) {
                const int n0 = (nt * 8 + g) * KSTR + s * 8 + qd;
                unsigned kb0 = Khi[n0], kb1 = Khi[n0 + 4];
                unsigned kl0 = Klo[n0], kl1 = Klo[n0 + 4];
                mma_bf16(sacc[nt], qhf[s][0], qhf[s][1], qhf[s][2], qhf[s][3], kb0, kb1);
                mma_bf16(sacc[nt], qhf[s][0], qhf[s][1], qhf[s][2], qhf[s][3], kl0, kl1);
                mma_bf16(sacc[nt], qlf[s][0], qlf[s][1], qlf[s][2], qlf[s][3], kb0, kb1);
            }
        }

        // softcap + mask + exp in fragments, pack P hi/lo
        unsigned phi[8][2], plo[8][2];
#pragma unroll
        for (int nt = 0; nt < 8; ++nt) {
            float p[4];
#pragma unroll
            for (int e = 0; e < 4; ++e) {
                const int key = (c << 6) + nt * 8 + 2 * qd + (e & 1);
                const int qg  = (e < 2) ? qrow : (qrow + 8);
                const float sv  = sacc[nt][e];
                const float scx = sv * 0.125f;   // ATTN_SCALE/SOFTCAP * SOFTCAP folded
                const float cap = scx - scx * scx * scx * (1.0f / 675.0f);
                const bool valid = (key <= qg) && ((key > qg - WINDOW) || (key < NGLOB));
                p[e] = valid ? __expf(cap) : 0.0f;
            }
            lsum0 += p[0] + p[1];
            lsum1 += p[2] + p[3];
            split2(p[0], p[1], phi[nt][0], plo[nt][0]);
            split2(p[2], p[3], phi[nt][1], plo[nt][1]);
        }

        // O += P V   (A-fragments = S C-fragments, FA2 identity)
#pragma unroll
        for (int s = 0; s < 4; ++s) {
            const unsigned a0h = phi[2 * s][0],     a1h = phi[2 * s][1];
            const unsigned a2h = phi[2 * s + 1][0], a3h = phi[2 * s + 1][1];
            const unsigned a0l = plo[2 * s][0],     a1l = plo[2 * s][1];
            const unsigned a2l = plo[2 * s + 1][0], a3l = plo[2 * s + 1][1];
#pragma unroll
            for (int nt = 0; nt < 8; ++nt) {
                const int n0 = (nt * 8 + g) * KSTR + s * 8 + qd;
                unsigned vb0 = Vthi[n0], vb1 = Vthi[n0 + 4];
                unsigned vl0 = Vtlo[n0], vl1 = Vtlo[n0 + 4];
                mma_bf16(oacc[nt], a0h, a1h, a2h, a3h, vb0, vb1);
                mma_bf16(oacc[nt], a0h, a1h, a2h, a3h, vl0, vl1);
                mma_bf16(oacc[nt], a0l, a1l, a2l, a3l, vb0, vb1);
            }
        }
        __syncthreads();
    }

    // reduce l across the 4 qd lanes (lane = 4*g + qd)
    lsum0 += __shfl_xor_sync(0xffffffffu, lsum0, 1);
    lsum0 += __shfl_xor_sync(0xffffffffu, lsum0, 2);
    lsum1 += __shfl_xor_sync(0xffffffffu, lsum1, 1);
    lsum1 += __shfl_xor_sync(0xffffffffu, lsum1, 2);
    const float i0 = 1.0f / lsum0;
    const float i1 = 1.0f / lsum1;

    float* Ob = g_ctx + ((size_t)(b * S_LEN + qrow) * NH + h) * DH;
#pragma unroll
    for (int nt = 0; nt < 8; ++nt) {
        float2 v0; v0.x = oacc[nt][0] * i0; v0.y = oacc[nt][1] * i0;
        float2 v1; v1.x = oacc[nt][2] * i1; v1.y = oacc[nt][3] * i1;
        *(float2*)(Ob + nt * 8 + 2 * qd) = v0;
        *(float2*)(Ob + 8 * NH * DH + nt * 8 + 2 * qd) = v1;   // row qrow+8
    }
}

// ---------------- launch ----------------
extern "C" void kernel_launch(void* const* d_in, const int* in_sizes, int n_in,
                              void* d_out, int out_size) {
    const float* x    = (const float*)d_in[0];
    const float* cosv = (const float*)d_in[1];
    const float* sinv = (const float*)d_in[2];
    // d_in[3] = mask (bool) — recomputed analytically
    const float* Wq   = (const float*)d_in[4];
    const float* Wk   = (const float*)d_in[5];
    const float* Wv   = (const float*)d_in[6];
    const float* Wo   = (const float*)d_in[7];
    float* out = (float*)d_out;

    // transpose weights to [N][K]; output buffer chosen by selector IN DEVICE CODE
    tr_kernel<<<dim3(32, 32), dim3(32, 8)>>>(Wq, 0, 1024, 1024);
    tr_kernel<<<dim3(8,  32), dim3(32, 8)>>>(Wk, 1, 1024, 256);
    tr_kernel<<<dim3(8,  32), dim3(32, 8)>>>(Wv, 2, 1024, 256);
    tr_kernel<<<dim3(32, 32), dim3(32, 8)>>>(Wo, 3, 1024, 1024);

    gemm_qkv_kernel<<<dim3(12, 32), 256>>>(x);

    const int nwarps  = BATCH * S_LEN * (NH + NKV);      // 81920
    const int nthread = nwarps * 32;
    normrope_kernel<<<(nthread + 255) / 256, 256>>>(cosv, sinv);

    attn_tc_kernel<<<dim3(S_LEN / 64, BATCH * NH), 128>>>();

    gemm_out_kernel<<<dim3(DMODEL / 128, (BATCH * S_LEN) / 128), 256>>>(out);
}

// round 9
// speedup vs baseline: 2.3535x; 1.0928x over previous
#include <cuda_runtime.h>
#include <cuda_bf16.h>

#define S_LEN   2048
#define BATCH   2
#define NH      16
#define NKV     4
#define DH      64
#define DMODEL  1024
#define WINDOW  256
#define NGLOB   4

// Scratch buffers (allocation-free rule: __device__ globals)
__device__ float g_q[BATCH * S_LEN * NH * DH];        // [tok,16,64]
__device__ float g_k[BATCH * S_LEN * NKV * DH];       // [tok,4,64]
__device__ float g_vt[NKV * DH * BATCH * S_LEN];      // TRANSPOSED V: [kvh*64+dh][tok]
__device__ float g_ctx[BATCH * S_LEN * NH * DH];      // [tok,1024]
// Transposed weights (B^T, row-major [N][K]) for mma.sync row.col
__device__ float g_wqt[1024 * 1024];
__device__ float g_wkt[256 * 1024];
__device__ float g_wvt[256 * 1024];
__device__ float g_wot[1024 * 1024];

// ---------------- merged weight transpose (one launch) ----------------
// grid.x: 0..31 Wq | 32..39 Wk | 40..47 Wv | 48..79 Wo ; grid.y = 32 (K/32)
// outputs are __device__ globals resolved in device code (never via host args).
__global__ __launch_bounds__(256) void tr_all_kernel(const float* __restrict__ Wq,
                                                     const float* __restrict__ Wk,
                                                     const float* __restrict__ Wv,
                                                     const float* __restrict__ Wo) {
    int bxi = blockIdx.x;
    const float* in; float* out; int C;
    if (bxi < 32)      { in = Wq; out = g_wqt; C = 1024; }
    else if (bxi < 40) { in = Wk; out = g_wkt; C = 256;  bxi -= 32; }
    else if (bxi < 48) { in = Wv; out = g_wvt; C = 256;  bxi -= 40; }
    else               { in = Wo; out = g_wot; C = 1024; bxi -= 48; }
    const int R = 1024;
    __shared__ float t[32][33];
    const int bx = bxi * 32, by = blockIdx.y * 32;
    const int x = bx + threadIdx.x;
#pragma unroll
    for (int i = threadIdx.y; i < 32; i += 8)
        t[i][threadIdx.x] = in[(by + i) * C + x];
    __syncthreads();
    const int xo = by + threadIdx.x;
#pragma unroll
    for (int i = threadIdx.y; i < 32; i += 8)
        out[(bx + i) * R + xo] = t[threadIdx.x][i];
}

// ---------------- bf16 helpers ----------------
__device__ __forceinline__ void split2(float x, float y, unsigned& hi, unsigned& lo) {
    __nv_bfloat16 hx = __float2bfloat16(x);
    __nv_bfloat16 hy = __float2bfloat16(y);
    __nv_bfloat16 lx = __float2bfloat16(x - __bfloat162float(hx));
    __nv_bfloat16 ly = __float2bfloat16(y - __bfloat162float(hy));
    hi = ((unsigned)__bfloat16_as_ushort(hy) << 16) | __bfloat16_as_ushort(hx);
    lo = ((unsigned)__bfloat16_as_ushort(ly) << 16) | __bfloat16_as_ushort(lx);
}
__device__ __forceinline__ unsigned packhi(float x, float y) {
    __nv_bfloat162 t = __floats2bfloat162_rn(x, y);   // .x = low half
    return *(unsigned*)&t;
}

__device__ __forceinline__ void mma_bf16(float* d, unsigned a0, unsigned a1,
                                         unsigned a2, unsigned a3,
                                         unsigned b0, unsigned b1) {
    asm volatile(
        "mma.sync.aligned.m16n8k16.row.col.f32.bf16.bf16.f32 "
        "{%0,%1,%2,%3}, {%4,%5,%6,%7}, {%8,%9}, {%0,%1,%2,%3};"
        : "+f"(d[0]), "+f"(d[1]), "+f"(d[2]), "+f"(d[3])
        : "r"(a0), "r"(a1), "r"(a2), "r"(a3), "r"(b0), "r"(b1));
}

// ---------------- bf16 tensor-core GEMM with hi/lo compensation ----------------
#define BKC   32
#define SSTR  20

__device__ __forceinline__ void gemm_tc_body(const float* __restrict__ A,
                                             const float* __restrict__ Bt,
                                             float* __restrict__ C,
                                             int N, int K, int bx, int by, int vt,
                                             unsigned* Ahi, unsigned* Alo,
                                             unsigned* Bhi, unsigned* Blo) {
    const int tid  = threadIdx.x;
    const int lane = tid & 31;
    const int warp = tid >> 5;
    const int grp  = lane >> 2;          // 0..7
    const int qd   = lane & 3;           // 0..3
    const int wm    = (warp >> 2) << 6;  // 0 or 64
    const int wncol = (warp & 3) << 5;   // 0,32,64,96

    A  += (size_t)by * 128 * K;
    Bt += (size_t)bx * 128 * K;

    float acc[4][4][4];
#pragma unroll
    for (int i = 0; i < 4; ++i)
#pragma unroll
        for (int j = 0; j < 4; ++j)
#pragma unroll
            for (int r = 0; r < 4; ++r) acc[i][j][r] = 0.0f;

    const int ldRow = tid >> 3;          // 0..31
    const int ldT   = tid & 7;           // 0..7 -> k = 4*ldT..+3

    for (int k0 = 0; k0 < K; k0 += BKC) {
#pragma unroll
        for (int i = 0; i < 4; ++i) {
            const int row = i * 32 + ldRow;
            float4 va = *(const float4*)(A  + (size_t)row * K + k0 + ldT * 4);
            float4 vb = *(const float4*)(Bt + (size_t)row * K + k0 + ldT * 4);
            unsigned h0, l0, h1, l1;
            split2(va.x, va.y, h0, l0);
            split2(va.z, va.w, h1, l1);
            Ahi[row * SSTR + ldT * 2]     = h0;
            Ahi[row * SSTR + ldT * 2 + 1] = h1;
            Alo[row * SSTR + ldT * 2]     = l0;
            Alo[row * SSTR + ldT * 2 + 1] = l1;
            split2(vb.x, vb.y, h0, l0);
            split2(vb.z, vb.w, h1, l1);
            Bhi[row * SSTR + ldT * 2]     = h0;
            Bhi[row * SSTR + ldT * 2 + 1] = h1;
            Blo[row * SSTR + ldT * 2]     = l0;
            Blo[row * SSTR + ldT * 2 + 1] = l1;
        }
        __syncthreads();

#pragma unroll
        for (int h = 0; h < 2; ++h) {      // two k16 steps per chunk
            unsigned ah[4][4], al[4][4], bh[4][2], bl[4][2];
#pragma unroll
            for (int mt = 0; mt < 4; ++mt) {
                const int r0 = (wm + mt * 16 + grp) * SSTR + h * 8 + qd;
                const int r1 = r0 + 8 * SSTR;
                ah[mt][0] = Ahi[r0];     ah[mt][1] = Ahi[r1];
                ah[mt][2] = Ahi[r0 + 4]; ah[mt][3] = Ahi[r1 + 4];
                al[mt][0] = Alo[r0];     al[mt][1] = Alo[r1];
                al[mt][2] = Alo[r0 + 4]; al[mt][3] = Alo[r1 + 4];
            }
#pragma unroll
            for (int nt = 0; nt < 4; ++nt) {
                const int n0 = (wncol + nt * 8 + grp) * SSTR + h * 8 + qd;
                bh[nt][0] = Bhi[n0]; bh[nt][1] = Bhi[n0 + 4];
                bl[nt][0] = Blo[n0]; bl[nt][1] = Blo[n0 + 4];
            }
#pragma unroll
            for (int mt = 0; mt < 4; ++mt)
#pragma unroll
                for (int nt = 0; nt < 4; ++nt) {
                    mma_bf16(acc[mt][nt], ah[mt][0], ah[mt][1], ah[mt][2], ah[mt][3],
                             bh[nt][0], bh[nt][1]);
                    mma_bf16(acc[mt][nt], ah[mt][0], ah[mt][1], ah[mt][2], ah[mt][3],
                             bl[nt][0], bl[nt][1]);
                    mma_bf16(acc[mt][nt], al[mt][0], al[mt][1], al[mt][2], al[mt][3],
                             bh[nt][0], bh[nt][1]);
                }
        }
        __syncthreads();
    }

    if (vt) {
#pragma unroll
        for (int mt = 0; mt < 4; ++mt)
#pragma unroll
            for (int nt = 0; nt < 4; ++nt) {
                const int row_g = by * 128 + wm + mt * 16 + grp;
                const int col_g = bx * 128 + wncol + nt * 8 + qd * 2;
                g_vt[(size_t)col_g       * (BATCH * S_LEN) + row_g]     = acc[mt][nt][0];
                g_vt[(size_t)(col_g + 1) * (BATCH * S_LEN) + row_g]     = acc[mt][nt][1];
                g_vt[(size_t)col_g       * (BATCH * S_LEN) + row_g + 8] = acc[mt][nt][2];
                g_vt[(size_t)(col_g + 1) * (BATCH * S_LEN) + row_g + 8] = acc[mt][nt][3];
            }
    } else {
        C += (size_t)by * 128 * N + bx * 128;
#pragma unroll
        for (int mt = 0; mt < 4; ++mt)
#pragma unroll
            for (int nt = 0; nt < 4; ++nt) {
                const int row = wm + mt * 16 + grp;
                const int col = wncol + nt * 8 + qd * 2;
                float2 lo; lo.x = acc[mt][nt][0]; lo.y = acc[mt][nt][1];
                float2 hi; hi.x = acc[mt][nt][2]; hi.y = acc[mt][nt][3];
                *(float2*)(C + (size_t)row * N + col)       = lo;
                *(float2*)(C + (size_t)(row + 8) * N + col) = hi;
            }
    }
}

// Fused QKV projection: grid.x 0..7 -> Q, 8..9 -> K, 10..11 -> V (transposed out)
__global__ __launch_bounds__(256) void gemm_qkv_kernel(const float* __restrict__ x) {
    __shared__ unsigned Ahi[128 * SSTR], Alo[128 * SSTR];
    __shared__ unsigned Bhi[128 * SSTR], Blo[128 * SSTR];
    const int bx = blockIdx.x, by = blockIdx.y;
    if (bx < 8)       gemm_tc_body(x, g_wqt, g_q, 1024, 1024, bx,      by, 0, Ahi, Alo, Bhi, Blo);
    else if (bx < 10) gemm_tc_body(x, g_wkt, g_k, 256,  1024, bx - 8,  by, 0, Ahi, Alo, Bhi, Blo);
    else              gemm_tc_body(x, g_wvt, g_vt, 256, 1024, bx - 10, by, 1, Ahi, Alo, Bhi, Blo);
}

__global__ __launch_bounds__(256) void gemm_out_kernel(float* __restrict__ out) {
    __shared__ unsigned Ahi[128 * SSTR], Alo[128 * SSTR];
    __shared__ unsigned Bhi[128 * SSTR], Blo[128 * SSTR];
    gemm_tc_body(g_ctx, g_wot, out, 1024, 1024, blockIdx.x, blockIdx.y, 0, Ahi, Alo, Bhi, Blo);
}

// ---------------- L2 normalize + RoPE (warp per token-head; Q and K only) ------
__global__ void normrope_kernel(const float* __restrict__ cosv,
                                const float* __restrict__ sinv) {
    const int gw   = (blockIdx.x * blockDim.x + threadIdx.x) >> 5;
    const int lane = threadIdx.x & 31;
    const int NQ   = BATCH * S_LEN * NH;
    const int NTOT = NQ + BATCH * S_LEN * NKV;
    if (gw >= NTOT) return;
    float* base;
    int tok;
    if (gw < NQ) { base = g_q + gw * DH; tok = gw / NH; }
    else         { int g2 = gw - NQ; base = g_k + g2 * DH; tok = g2 / NKV; }
    const int s = tok & (S_LEN - 1);

    float x1 = base[lane];
    float x2 = base[lane + 32];
    float ss = x1 * x1 + x2 * x2;
#pragma unroll
    for (int o = 16; o; o >>= 1) ss += __shfl_xor_sync(0xffffffffu, ss, o);
    const float inv = 1.0f / (sqrtf(ss) + 1e-8f);
    x1 *= inv; x2 *= inv;
    const float c  = cosv[s * 32 + lane];
    const float sn = sinv[s * 32 + lane];
    base[lane]      = x1 * c - x2 * sn;
    base[lane + 32] = x1 * sn + x2 * c;
}

// ---------------- Tensor-core attention (4 heads of a KV group per block) ------
// 512 threads = 16 warps; warp w: head = kh*4 + (w>>2), q-row group = (w&3)*16.
// Shared K/V chunk staged ONCE per block for all 4 heads.
// S = Q K^T: 1-pass bf16 (score err folded by ATTN_SCALE -> negligible).
// PV: 3-pass hi/lo (output is a cancel-heavy average; needs compensation).
#define KSTR 36

__global__ __launch_bounds__(512, 1) void attn_tc_kernel() {
    __shared__ unsigned Khi[64 * KSTR];
    __shared__ unsigned Vthi[64 * KSTR], Vtlo[64 * KSTR];
    const int tid  = threadIdx.x;
    const int lane = tid & 31;
    const int w    = tid >> 5;       // 0..15
    const int g    = lane >> 2;
    const int qd   = lane & 3;
    const int wq   = w & 3;          // q-row group within tile
    const int hs   = w >> 2;         // head within kv group
    const int b    = blockIdx.y >> 2;
    const int kh   = blockIdx.y & 3;
    const int h    = (kh << 2) + hs;
    const int qb   = blockIdx.x << 6;        // 64-query tile base
    const int qrow = qb + (wq << 4) + g;     // rows qrow and qrow+8

    // Q A-fragments (hi only) for 4 k-steps over dh
    unsigned qhf[4][4];
    {
        const float* Qb = g_q + ((size_t)(b * S_LEN + qb + (wq << 4)) * NH + h) * DH;
#pragma unroll
        for (int s = 0; s < 4; ++s) {
            float2 f0 = *(const float2*)(Qb + g * 1024 + s * 16 + 2 * qd);
            float2 f1 = *(const float2*)(Qb + (g + 8) * 1024 + s * 16 + 2 * qd);
            float2 f2 = *(const float2*)(Qb + g * 1024 + s * 16 + 8 + 2 * qd);
            float2 f3 = *(const float2*)(Qb + (g + 8) * 1024 + s * 16 + 8 + 2 * qd);
            qhf[s][0] = packhi(f0.x, f0.y);
            qhf[s][1] = packhi(f1.x, f1.y);
            qhf[s][2] = packhi(f2.x, f2.y);
            qhf[s][3] = packhi(f3.x, f3.y);
        }
    }

    float oacc[8][4];
#pragma unroll
    for (int i = 0; i < 8; ++i)
#pragma unroll
        for (int j = 0; j < 4; ++j) oacc[i][j] = 0.0f;
    float lsum0 = 0.0f, lsum1 = 0.0f;

    const int lo_chunk = (qb > (WINDOW - 1)) ? ((qb - (WINDOW - 1)) >> 6) : 0;
    const int hi_chunk = qb >> 6;

    for (int c = 0; c <= hi_chunk; ++c) {
        if (c > 0 && c < lo_chunk) continue;   // uniform across block
        // stage K chunk (hi only) and V chunk (hi/lo) — shared by all 4 heads
        {
            const float* Kb = g_k + ((size_t)(b * S_LEN + (c << 6)) * NKV + kh) * DH;
#pragma unroll
            for (int r = 0; r < 2; ++r) {
                const int idx = (r << 9) + tid;          // 0..1023
                const int row = idx >> 4, c4 = idx & 15;
                float4 v = *(const float4*)(Kb + (size_t)row * (NKV * DH) + c4 * 4);
                Khi[row * KSTR + c4 * 2]     = packhi(v.x, v.y);
                Khi[row * KSTR + c4 * 2 + 1] = packhi(v.z, v.w);
            }
            const float* Vb = g_vt + (size_t)(kh * DH) * (BATCH * S_LEN)
                            + b * S_LEN + (c << 6);
#pragma unroll
            for (int r = 0; r < 2; ++r) {
                const int idx = (r << 9) + tid;
                const int row = idx >> 4, c4 = idx & 15;     // row = dh
                float4 v = *(const float4*)(Vb + (size_t)row * (BATCH * S_LEN) + c4 * 4);
                unsigned h0, l0, h1, l1;
                split2(v.x, v.y, h0, l0);
                split2(v.z, v.w, h1, l1);
                Vthi[row * KSTR + c4 * 2]     = h0;
                Vthi[row * KSTR + c4 * 2 + 1] = h1;
                Vtlo[row * KSTR + c4 * 2]     = l0;
                Vtlo[row * KSTR + c4 * 2 + 1] = l1;
            }
        }
        __syncthreads();

        // S = Q K^T  (1-pass bf16; warp: 16 q-rows x 64 keys)
        float sacc[8][4];
#pragma unroll
        for (int i = 0; i < 8; ++i)
#pragma unroll
            for (int j = 0; j < 4; ++j) sacc[i][j] = 0.0f;
#pragma unroll
        for (int s = 0; s < 4; ++s) {
#pragma unroll
            for (int nt = 0; nt < 8; ++nt) {
                const int n0 = (nt * 8 + g) * KSTR + s * 8 + qd;
                mma_bf16(sacc[nt], qhf[s][0], qhf[s][1], qhf[s][2], qhf[s][3],
                         Khi[n0], Khi[n0 + 4]);
            }
        }

        // softcap + mask + exp in fragments, pack P hi/lo
        unsigned phi[8][2], plo[8][2];
#pragma unroll
        for (int nt = 0; nt < 8; ++nt) {
            float p[4];
#pragma unroll
            for (int e = 0; e < 4; ++e) {
                const int key = (c << 6) + nt * 8 + 2 * qd + (e & 1);
                const int qg  = (e < 2) ? qrow : (qrow + 8);
                const float sv  = sacc[nt][e];
                const float scx = sv * 0.125f;   // ATTN_SCALE/SOFTCAP * SOFTCAP folded
                const float cap = scx - scx * scx * scx * (1.0f / 675.0f);
                const bool valid = (key <= qg) && ((key > qg - WINDOW) || (key < NGLOB));
                p[e] = valid ? __expf(cap) : 0.0f;
            }
            lsum0 += p[0] + p[1];
            lsum1 += p[2] + p[3];
            split2(p[0], p[1], phi[nt][0], plo[nt][0]);
            split2(p[2], p[3], phi[nt][1], plo[nt][1]);
        }

        // O += P V   (A-fragments = S C-fragments, FA2 identity; 3-pass)
#pragma unroll
        for (int s = 0; s < 4; ++s) {
            const unsigned a0h = phi[2 * s][0],     a1h = phi[2 * s][1];
            const unsigned a2h = phi[2 * s + 1][0], a3h = phi[2 * s + 1][1];
            const unsigned a0l = plo[2 * s][0],     a1l = plo[2 * s][1];
            const unsigned a2l = plo[2 * s + 1][0], a3l = plo[2 * s + 1][1];
#pragma unroll
            for (int nt = 0; nt < 8; ++nt) {
                const int n0 = (nt * 8 + g) * KSTR + s * 8 + qd;
                unsigned vb0 = Vthi[n0], vb1 = Vthi[n0 + 4];
                unsigned vl0 = Vtlo[n0], vl1 = Vtlo[n0 + 4];
                mma_bf16(oacc[nt], a0h, a1h, a2h, a3h, vb0, vb1);
                mma_bf16(oacc[nt], a0h, a1h, a2h, a3h, vl0, vl1);
                mma_bf16(oacc[nt], a0l, a1l, a2l, a3l, vb0, vb1);
            }
        }
        __syncthreads();
    }

    // reduce l across the 4 qd lanes (lane = 4*g + qd)
    lsum0 += __shfl_xor_sync(0xffffffffu, lsum0, 1);
    lsum0 += __shfl_xor_sync(0xffffffffu, lsum0, 2);
    lsum1 += __shfl_xor_sync(0xffffffffu, lsum1, 1);
    lsum1 += __shfl_xor_sync(0xffffffffu, lsum1, 2);
    const float i0 = 1.0f / lsum0;
    const float i1 = 1.0f / lsum1;

    float* Ob = g_ctx + ((size_t)(b * S_LEN + qrow) * NH + h) * DH;
#pragma unroll
    for (int nt = 0; nt < 8; ++nt) {
        float2 v0; v0.x = oacc[nt][0] * i0; v0.y = oacc[nt][1] * i0;
        float2 v1; v1.x = oacc[nt][2] * i1; v1.y = oacc[nt][3] * i1;
        *(float2*)(Ob + nt * 8 + 2 * qd) = v0;
        *(float2*)(Ob + 8 * NH * DH + nt * 8 + 2 * qd) = v1;   // row qrow+8
    }
}

// ---------------- launch ----------------
extern "C" void kernel_launch(void* const* d_in, const int* in_sizes, int n_in,
                              void* d_out, int out_size) {
    const float* x    = (const float*)d_in[0];
    const float* cosv = (const float*)d_in[1];
    const float* sinv = (const float*)d_in[2];
    // d_in[3] = mask (bool) — recomputed analytically
    const float* Wq   = (const float*)d_in[4];
    const float* Wk   = (const float*)d_in[5];
    const float* Wv   = (const float*)d_in[6];
    const float* Wo   = (const float*)d_in[7];
    float* out = (float*)d_out;

    tr_all_kernel<<<dim3(80, 32), dim3(32, 8)>>>(Wq, Wk, Wv, Wo);

    gemm_qkv_kernel<<<dim3(12, 32), 256>>>(x);

    const int nwarps  = BATCH * S_LEN * (NH + NKV);      // 81920
    const int nthread = nwarps * 32;
    normrope_kernel<<<(nthread + 255) / 256, 256>>>(cosv, sinv);

    attn_tc_kernel<<<dim3(S_LEN / 64, BATCH * NKV), 512>>>();

    gemm_out_kernel<<<dim3(DMODEL / 128, (BATCH * S_LEN) / 128), 256>>>(out);
}

// round 12
// speedup vs baseline: 3.0610x; 1.3006x over previous
#include <cuda_runtime.h>
#include <cuda_bf16.h>

#define S_LEN   2048
#define BATCH   2
#define NH      16
#define NKV     4
#define DH      64
#define DMODEL  1024
#define WINDOW  256
#define NGLOB   4

// Scratch buffers (allocation-free rule: __device__ globals)
__device__ float g_q[BATCH * S_LEN * NH * DH];        // [tok,16,64]
__device__ float g_k[BATCH * S_LEN * NKV * DH];       // [tok,4,64]
__device__ float g_vt[NKV * DH * BATCH * S_LEN];      // TRANSPOSED V: [kvh*64+dh][tok]
__device__ float g_ctx[BATCH * S_LEN * NH * DH];      // [tok,1024]
// Transposed weights (B^T, row-major [N][K]) for mma.sync row.col
__device__ float g_wqt[1024 * 1024];
__device__ float g_wkt[256 * 1024];
__device__ float g_wvt[256 * 1024];
__device__ float g_wot[1024 * 1024];

// ---------------- merged weight transpose (one launch) ----------------
__global__ __launch_bounds__(256) void tr_all_kernel(const float* __restrict__ Wq,
                                                     const float* __restrict__ Wk,
                                                     const float* __restrict__ Wv,
                                                     const float* __restrict__ Wo) {
    int bxi = blockIdx.x;
    const float* in; float* out; int C;
    if (bxi < 32)      { in = Wq; out = g_wqt; C = 1024; }
    else if (bxi < 40) { in = Wk; out = g_wkt; C = 256;  bxi -= 32; }
    else if (bxi < 48) { in = Wv; out = g_wvt; C = 256;  bxi -= 40; }
    else               { in = Wo; out = g_wot; C = 1024; bxi -= 48; }
    const int R = 1024;
    __shared__ float t[32][33];
    const int bx = bxi * 32, by = blockIdx.y * 32;
    const int x = bx + threadIdx.x;
#pragma unroll
    for (int i = threadIdx.y; i < 32; i += 8)
        t[i][threadIdx.x] = in[(by + i) * C + x];
    __syncthreads();
    const int xo = by + threadIdx.x;
#pragma unroll
    for (int i = threadIdx.y; i < 32; i += 8)
        out[(bx + i) * R + xo] = t[threadIdx.x][i];
}

// ---------------- bf16 helpers ----------------
__device__ __forceinline__ void split2(float x, float y, unsigned& hi, unsigned& lo) {
    __nv_bfloat16 hx = __float2bfloat16(x);
    __nv_bfloat16 hy = __float2bfloat16(y);
    __nv_bfloat16 lx = __float2bfloat16(x - __bfloat162float(hx));
    __nv_bfloat16 ly = __float2bfloat16(y - __bfloat162float(hy));
    hi = ((unsigned)__bfloat16_as_ushort(hy) << 16) | __bfloat16_as_ushort(hx);
    lo = ((unsigned)__bfloat16_as_ushort(ly) << 16) | __bfloat16_as_ushort(lx);
}
__device__ __forceinline__ unsigned packhi(float x, float y) {
    __nv_bfloat162 t = __floats2bfloat162_rn(x, y);   // .x = low half
    return *(unsigned*)&t;
}

__device__ __forceinline__ void mma_bf16(float* d, unsigned a0, unsigned a1,
                                         unsigned a2, unsigned a3,
                                         unsigned b0, unsigned b1) {
    asm volatile(
        "mma.sync.aligned.m16n8k16.row.col.f32.bf16.bf16.f32 "
        "{%0,%1,%2,%3}, {%4,%5,%6,%7}, {%8,%9}, {%0,%1,%2,%3};"
        : "+f"(d[0]), "+f"(d[1]), "+f"(d[2]), "+f"(d[3])
        : "r"(a0), "r"(a1), "r"(a2), "r"(a3), "r"(b0), "r"(b1));
}

// ---------------- bf16 tensor-core GEMM (1-pass or 3-pass hi/lo) ----------------
// passes==3: Ahi*Bhi + Ahi*Blo + Alo*Bhi (rel err ~4e-6)
// passes==1: Ahi*Bhi only (rel err ~2e-3) — ONLY for Q/K whose error is
//            attenuated by L2-normalization + ATTN_SCALE folding downstream.
#define BKC   32
#define SSTR  20

__device__ __forceinline__ void gemm_tc_body(const float* __restrict__ A,
                                             const float* __restrict__ Bt,
                                             float* __restrict__ C,
                                             int N, int K, int bx, int by,
                                             int vt, int passes,
                                             unsigned* Ahi, unsigned* Alo,
                                             unsigned* Bhi, unsigned* Blo) {
    const int tid  = threadIdx.x;
    const int lane = tid & 31;
    const int warp = tid >> 5;
    const int grp  = lane >> 2;          // 0..7
    const int qd   = lane & 3;           // 0..3
    const int wm    = (warp >> 2) << 6;  // 0 or 64
    const int wncol = (warp & 3) << 5;   // 0,32,64,96

    A  += (size_t)by * 128 * K;
    Bt += (size_t)bx * 128 * K;

    float acc[4][4][4];
#pragma unroll
    for (int i = 0; i < 4; ++i)
#pragma unroll
        for (int j = 0; j < 4; ++j)
#pragma unroll
            for (int r = 0; r < 4; ++r) acc[i][j][r] = 0.0f;

    const int ldRow = tid >> 3;          // 0..31
    const int ldT   = tid & 7;           // 0..7 -> k = 4*ldT..+3

    for (int k0 = 0; k0 < K; k0 += BKC) {
#pragma unroll
        for (int i = 0; i < 4; ++i) {
            const int row = i * 32 + ldRow;
            float4 va = *(const float4*)(A  + (size_t)row * K + k0 + ldT * 4);
            float4 vb = *(const float4*)(Bt + (size_t)row * K + k0 + ldT * 4);
            if (passes == 3) {
                unsigned h0, l0, h1, l1;
                split2(va.x, va.y, h0, l0);
                split2(va.z, va.w, h1, l1);
                Ahi[row * SSTR + ldT * 2]     = h0;
                Ahi[row * SSTR + ldT * 2 + 1] = h1;
                Alo[row * SSTR + ldT * 2]     = l0;
                Alo[row * SSTR + ldT * 2 + 1] = l1;
                split2(vb.x, vb.y, h0, l0);
                split2(vb.z, vb.w, h1, l1);
                Bhi[row * SSTR + ldT * 2]     = h0;
                Bhi[row * SSTR + ldT * 2 + 1] = h1;
                Blo[row * SSTR + ldT * 2]     = l0;
                Blo[row * SSTR + ldT * 2 + 1] = l1;
            } else {
                Ahi[row * SSTR + ldT * 2]     = packhi(va.x, va.y);
                Ahi[row * SSTR + ldT * 2 + 1] = packhi(va.z, va.w);
                Bhi[row * SSTR + ldT * 2]     = packhi(vb.x, vb.y);
                Bhi[row * SSTR + ldT * 2 + 1] = packhi(vb.z, vb.w);
            }
        }
        __syncthreads();

#pragma unroll
        for (int h = 0; h < 2; ++h) {      // two k16 steps per chunk
            unsigned ah[4][4], bh[4][2];
#pragma unroll
            for (int mt = 0; mt < 4; ++mt) {
                const int r0 = (wm + mt * 16 + grp) * SSTR + h * 8 + qd;
                const int r1 = r0 + 8 * SSTR;
                ah[mt][0] = Ahi[r0];     ah[mt][1] = Ahi[r1];
                ah[mt][2] = Ahi[r0 + 4]; ah[mt][3] = Ahi[r1 + 4];
            }
#pragma unroll
            for (int nt = 0; nt < 4; ++nt) {
                const int n0 = (wncol + nt * 8 + grp) * SSTR + h * 8 + qd;
                bh[nt][0] = Bhi[n0]; bh[nt][1] = Bhi[n0 + 4];
            }
#pragma unroll
            for (int mt = 0; mt < 4; ++mt)
#pragma unroll
                for (int nt = 0; nt < 4; ++nt)
                    mma_bf16(acc[mt][nt], ah[mt][0], ah[mt][1], ah[mt][2], ah[mt][3],
                             bh[nt][0], bh[nt][1]);
            if (passes == 3) {
                unsigned al[4][4], bl[4][2];
#pragma unroll
                for (int mt = 0; mt < 4; ++mt) {
                    const int r0 = (wm + mt * 16 + grp) * SSTR + h * 8 + qd;
                    const int r1 = r0 + 8 * SSTR;
                    al[mt][0] = Alo[r0];     al[mt][1] = Alo[r1];
                    al[mt][2] = Alo[r0 + 4]; al[mt][3] = Alo[r1 + 4];
                }
#pragma unroll
                for (int nt = 0; nt < 4; ++nt) {
                    const int n0 = (wncol + nt * 8 + grp) * SSTR + h * 8 + qd;
                    bl[nt][0] = Blo[n0]; bl[nt][1] = Blo[n0 + 4];
                }
#pragma unroll
                for (int mt = 0; mt < 4; ++mt)
#pragma unroll
                    for (int nt = 0; nt < 4; ++nt) {
                        mma_bf16(acc[mt][nt], ah[mt][0], ah[mt][1], ah[mt][2], ah[mt][3],
                                 bl[nt][0], bl[nt][1]);
                        mma_bf16(acc[mt][nt], al[mt][0], al[mt][1], al[mt][2], al[mt][3],
                                 bh[nt][0], bh[nt][1]);
                    }
            }
        }
        __syncthreads();
    }

    if (vt) {
#pragma unroll
        for (int mt = 0; mt < 4; ++mt)
#pragma unroll
            for (int nt = 0; nt < 4; ++nt) {
                const int row_g = by * 128 + wm + mt * 16 + grp;
                const int col_g = bx * 128 + wncol + nt * 8 + qd * 2;
                g_vt[(size_t)col_g       * (BATCH * S_LEN) + row_g]     = acc[mt][nt][0];
                g_vt[(size_t)(col_g + 1) * (BATCH * S_LEN) + row_g]     = acc[mt][nt][1];
                g_vt[(size_t)col_g       * (BATCH * S_LEN) + row_g + 8] = acc[mt][nt][2];
                g_vt[(size_t)(col_g + 1) * (BATCH * S_LEN) + row_g + 8] = acc[mt][nt][3];
            }
    } else {
        C += (size_t)by * 128 * N + bx * 128;
#pragma unroll
        for (int mt = 0; mt < 4; ++mt)
#pragma unroll
            for (int nt = 0; nt < 4; ++nt) {
                const int row = wm + mt * 16 + grp;
                const int col = wncol + nt * 8 + qd * 2;
                float2 lo; lo.x = acc[mt][nt][0]; lo.y = acc[mt][nt][1];
                float2 hi; hi.x = acc[mt][nt][2]; hi.y = acc[mt][nt][3];
                *(float2*)(C + (size_t)row * N + col)       = lo;
                *(float2*)(C + (size_t)(row + 8) * N + col) = hi;
            }
    }
}

// Fused QKV projection: grid.x 0..7 -> Q (1-pass), 8..9 -> K (1-pass),
//                       10..11 -> V (3-pass, transposed out)
__global__ __launch_bounds__(256) void gemm_qkv_kernel(const float* __restrict__ x) {
    __shared__ unsigned Ahi[128 * SSTR], Alo[128 * SSTR];
    __shared__ unsigned Bhi[128 * SSTR], Blo[128 * SSTR];
    const int bx = blockIdx.x, by = blockIdx.y;
    if (bx < 8)       gemm_tc_body(x, g_wqt, g_q, 1024, 1024, bx,      by, 0, 1, Ahi, Alo, Bhi, Blo);
    else if (bx < 10) gemm_tc_body(x, g_wkt, g_k, 256,  1024, bx - 8,  by, 0, 1, Ahi, Alo, Bhi, Blo);
    else              gemm_tc_body(x, g_wvt, g_vt, 256, 1024, bx - 10, by, 1, 3, Ahi, Alo, Bhi, Blo);
}

__global__ __launch_bounds__(256) void gemm_out_kernel(float* __restrict__ out) {
    __shared__ unsigned Ahi[128 * SSTR], Alo[128 * SSTR];
    __shared__ unsigned Bhi[128 * SSTR], Blo[128 * SSTR];
    gemm_tc_body(g_ctx, g_wot, out, 1024, 1024, blockIdx.x, blockIdx.y, 0, 3,
                 Ahi, Alo, Bhi, Blo);
}

// ---------------- L2 normalize + RoPE (warp per token-head; Q and K only) ------
__global__ void normrope_kernel(const float* __restrict__ cosv,
                                const float* __restrict__ sinv) {
    const int gw   = (blockIdx.x * blockDim.x + threadIdx.x) >> 5;
    const int lane = threadIdx.x & 31;
    const int NQ   = BATCH * S_LEN * NH;
    const int NTOT = NQ + BATCH * S_LEN * NKV;
    if (gw >= NTOT) return;
    float* base;
    int tok;
    if (gw < NQ) { base = g_q + gw * DH; tok = gw / NH; }
    else         { int g2 = gw - NQ; base = g_k + g2 * DH; tok = g2 / NKV; }
    const int s = tok & (S_LEN - 1);

    float x1 = base[lane];
    float x2 = base[lane + 32];
    float ss = x1 * x1 + x2 * x2;
#pragma unroll
    for (int o = 16; o; o >>= 1) ss += __shfl_xor_sync(0xffffffffu, ss, o);
    const float inv = 1.0f / (sqrtf(ss) + 1e-8f);
    x1 *= inv; x2 *= inv;
    const float c  = cosv[s * 32 + lane];
    const float sn = sinv[s * 32 + lane];
    base[lane]      = x1 * c - x2 * sn;
    base[lane + 32] = x1 * sn + x2 * c;
}

// ---------------- Tensor-core attention (2 heads of a KV group per block) ------
// 256 threads = 8 warps; warp w: head-slot = w>>2, q-row group = (w&3)*16.
// 2 CTAs/SM (32k regs each) for latency overlap; K/V chunk shared by 2 heads.
// S = Q K^T: 1-pass bf16. PV: 3-pass hi/lo.
#define KSTR 36

__global__ __launch_bounds__(256, 2) void attn_tc_kernel() {
    __shared__ unsigned Khi[64 * KSTR];
    __shared__ unsigned Vthi[64 * KSTR], Vtlo[64 * KSTR];
    const int tid  = threadIdx.x;
    const int lane = tid & 31;
    const int w    = tid >> 5;       // 0..7
    const int g    = lane >> 2;
    const int qd   = lane & 3;
    const int wq   = w & 3;          // q-row group within tile
    const int hs   = w >> 2;         // head slot (0..1)
    const int by   = blockIdx.y;     // 0..15
    const int b    = by >> 3;
    const int kh   = (by >> 1) & 3;
    const int hp   = by & 1;
    const int h    = (kh << 2) + (hp << 1) + hs;
    const int qb   = blockIdx.x << 6;        // 64-query tile base
    const int qrow = qb + (wq << 4) + g;     // rows qrow and qrow+8

    // Q A-fragments (hi only) for 4 k-steps over dh
    unsigned qhf[4][4];
    {
        const float* Qb = g_q + ((size_t)(b * S_LEN + qb + (wq << 4)) * NH + h) * DH;
#pragma unroll
        for (int s = 0; s < 4; ++s) {
            float2 f0 = *(const float2*)(Qb + g * 1024 + s * 16 + 2 * qd);
            float2 f1 = *(const float2*)(Qb + (g + 8) * 1024 + s * 16 + 2 * qd);
            float2 f2 = *(const float2*)(Qb + g * 1024 + s * 16 + 8 + 2 * qd);
            float2 f3 = *(const float2*)(Qb + (g + 8) * 1024 + s * 16 + 8 + 2 * qd);
            qhf[s][0] = packhi(f0.x, f0.y);
            qhf[s][1] = packhi(f1.x, f1.y);
            qhf[s][2] = packhi(f2.x, f2.y);
            qhf[s][3] = packhi(f3.x, f3.y);
        }
    }

    float oacc[8][4];
#pragma unroll
    for (int i = 0; i < 8; ++i)
#pragma unroll
        for (int j = 0; j < 4; ++j) oacc[i][j] = 0.0f;
    float lsum0 = 0.0f, lsum1 = 0.0f;

    const int lo_chunk = (qb > (WINDOW - 1)) ? ((qb - (WINDOW - 1)) >> 6) : 0;
    const int hi_chunk = qb >> 6;

    for (int c = 0; c <= hi_chunk; ++c) {
        if (c > 0 && c < lo_chunk) continue;   // uniform across block
        // stage K chunk (hi only) and V chunk (hi/lo) — shared by both heads
        {
            const float* Kb = g_k + ((size_t)(b * S_LEN + (c << 6)) * NKV + kh) * DH;
#pragma unroll
            for (int r = 0; r < 4; ++r) {
                const int idx = (r << 8) + tid;          // 0..1023
                const int row = idx >> 4, c4 = idx & 15;
                float4 v = *(const float4*)(Kb + (size_t)row * (NKV * DH) + c4 * 4);
                Khi[row * KSTR + c4 * 2]     = packhi(v.x, v.y);
                Khi[row * KSTR + c4 * 2 + 1] = packhi(v.z, v.w);
            }
            const float* Vb = g_vt + (size_t)(kh * DH) * (BATCH * S_LEN)
                            + b * S_LEN + (c << 6);
#pragma unroll
            for (int r = 0; r < 4; ++r) {
                const int idx = (r << 8) + tid;
                const int row = idx >> 4, c4 = idx & 15;     // row = dh
                float4 v = *(const float4*)(Vb + (size_t)row * (BATCH * S_LEN) + c4 * 4);
                unsigned h0, l0, h1, l1;
                split2(v.x, v.y, h0, l0);
                split2(v.z, v.w, h1, l1);
                Vthi[row * KSTR + c4 * 2]     = h0;
                Vthi[row * KSTR + c4 * 2 + 1] = h1;
                Vtlo[row * KSTR + c4 * 2]     = l0;
                Vtlo[row * KSTR + c4 * 2 + 1] = l1;
            }
        }
        __syncthreads();

        // S = Q K^T  (1-pass bf16; warp: 16 q-rows x 64 keys)
        float sacc[8][4];
#pragma unroll
        for (int i = 0; i < 8; ++i)
#pragma unroll
            for (int j = 0; j < 4; ++j) sacc[i][j] = 0.0f;
#pragma unroll
        for (int s = 0; s < 4; ++s) {
#pragma unroll
            for (int nt = 0; nt < 8; ++nt) {
                const int n0 = (nt * 8 + g) * KSTR + s * 8 + qd;
                mma_bf16(sacc[nt], qhf[s][0], qhf[s][1], qhf[s][2], qhf[s][3],
                         Khi[n0], Khi[n0 + 4]);
            }
        }

        // softcap + mask + exp in fragments, pack P hi/lo
        unsigned phi[8][2], plo[8][2];
#pragma unroll
        for (int nt = 0; nt < 8; ++nt) {
            float p[4];
#pragma unroll
            for (int e = 0; e < 4; ++e) {
                const int key = (c << 6) + nt * 8 + 2 * qd + (e & 1);
                const int qg  = (e < 2) ? qrow : (qrow + 8);
                const float sv  = sacc[nt][e];
                const float scx = sv * 0.125f;
                const float cap = scx - scx * scx * scx * (1.0f / 675.0f);
                const bool valid = (key <= qg) && ((key > qg - WINDOW) || (key < NGLOB));
                p[e] = valid ? __expf(cap) : 0.0f;
            }
            lsum0 += p[0] + p[1];
            lsum1 += p[2] + p[3];
            split2(p[0], p[1], phi[nt][0], plo[nt][0]);
            split2(p[2], p[3], phi[nt][1], plo[nt][1]);
        }

        // O += P V   (A-fragments = S C-fragments, FA2 identity; 3-pass)
#pragma unroll
        for (int s = 0; s < 4; ++s) {
            const unsigned a0h = phi[2 * s][0],     a1h = phi[2 * s][1];
            const unsigned a2h = phi[2 * s + 1][0], a3h = phi[2 * s + 1][1];
            const unsigned a0l = plo[2 * s][0],     a1l = plo[2 * s][1];
            const unsigned a2l = plo[2 * s + 1][0], a3l = plo[2 * s + 1][1];
#pragma unroll
            for (int nt = 0; nt < 8; ++nt) {
                const int n0 = (nt * 8 + g) * KSTR + s * 8 + qd;
                unsigned vb0 = Vthi[n0], vb1 = Vthi[n0 + 4];
                unsigned vl0 = Vtlo[n0], vl1 = Vtlo[n0 + 4];
                mma_bf16(oacc[nt], a0h, a1h, a2h, a3h, vb0, vb1);
                mma_bf16(oacc[nt], a0h, a1h, a2h, a3h, vl0, vl1);
                mma_bf16(oacc[nt], a0l, a1l, a2l, a3l, vb0, vb1);
            }
        }
        __syncthreads();
    }

    // reduce l across the 4 qd lanes (lane = 4*g + qd)
    lsum0 += __shfl_xor_sync(0xffffffffu, lsum0, 1);
    lsum0 += __shfl_xor_sync(0xffffffffu, lsum0, 2);
    lsum1 += __shfl_xor_sync(0xffffffffu, lsum1, 1);
    lsum1 += __shfl_xor_sync(0xffffffffu, lsum1, 2);
    const float i0 = 1.0f / lsum0;
    const float i1 = 1.0f / lsum1;

    float* Ob = g_ctx + ((size_t)(b * S_LEN + qrow) * NH + h) * DH;
#pragma unroll
    for (int nt = 0; nt < 8; ++nt) {
        float2 v0; v0.x = oacc[nt][0] * i0; v0.y = oacc[nt][1] * i0;
        float2 v1; v1.x = oacc[nt][2] * i1; v1.y = oacc[nt][3] * i1;
        *(float2*)(Ob + nt * 8 + 2 * qd) = v0;
        *(float2*)(Ob + 8 * NH * DH + nt * 8 + 2 * qd) = v1;   // row qrow+8
    }
}

// ---------------- launch ----------------
extern "C" void kernel_launch(void* const* d_in, const int* in_sizes, int n_in,
                              void* d_out, int out_size) {
    const float* x    = (const float*)d_in[0];
    const float* cosv = (const float*)d_in[1];
    const float* sinv = (const float*)d_in[2];
    // d_in[3] = mask (bool) — recomputed analytically
    const float* Wq   = (const float*)d_in[4];
    const float* Wk   = (const float*)d_in[5];
    const float* Wv   = (const float*)d_in[6];
    const float* Wo   = (const float*)d_in[7];
    float* out = (float*)d_out;

    tr_all_kernel<<<dim3(80, 32), dim3(32, 8)>>>(Wq, Wk, Wv, Wo);

    gemm_qkv_kernel<<<dim3(12, 32), 256>>>(x);

    const int nwarps  = BATCH * S_LEN * (NH + NKV);      // 81920
    const int nthread = nwarps * 32;
    normrope_kernel<<<(nthread + 255) / 256, 256>>>(cosv, sinv);

    attn_tc_kernel<<<dim3(S_LEN / 64, BATCH * NKV * 2), 256>>>();

    gemm_out_kernel<<<dim3(DMODEL / 128, (BATCH * S_LEN) / 128), 256>>>(out);
}

// round 14
// speedup vs baseline: 3.1329x; 1.0235x over previous
#include <cuda_runtime.h>
#include <cuda_bf16.h>

#define S_LEN   2048
#define BATCH   2
#define NH      16
#define NKV     4
#define DH      64
#define DMODEL  1024
#define WINDOW  256
#define NGLOB   4

typedef unsigned long long ull;

// Scratch buffers (allocation-free rule: __device__ globals)
__device__ float g_q[BATCH * S_LEN * NH * DH];        // [tok,16,64]
__device__ float g_k[BATCH * S_LEN * NKV * DH];       // [tok,4,64]
__device__ float g_vt[NKV * DH * BATCH * S_LEN];      // TRANSPOSED V: [kvh*64+dh][tok]
__device__ float g_ctx[BATCH * S_LEN * NH * DH];      // [tok,1024]
// Transposed weights (B^T, row-major [N][K]) for mma.sync row.col
__device__ float g_wqt[1024 * 1024];
__device__ float g_wkt[256 * 1024];
__device__ float g_wvt[256 * 1024];
__device__ float g_wot[1024 * 1024];

// ---------------- merged weight transpose (one launch) ----------------
__global__ __launch_bounds__(256) void tr_all_kernel(const float* __restrict__ Wq,
                                                     const float* __restrict__ Wk,
                                                     const float* __restrict__ Wv,
                                                     const float* __restrict__ Wo) {
    int bxi = blockIdx.x;
    const float* in; float* out; int C;
    if (bxi < 32)      { in = Wq; out = g_wqt; C = 1024; }
    else if (bxi < 40) { in = Wk; out = g_wkt; C = 256;  bxi -= 32; }
    else if (bxi < 48) { in = Wv; out = g_wvt; C = 256;  bxi -= 40; }
    else               { in = Wo; out = g_wot; C = 1024; bxi -= 48; }
    const int R = 1024;
    __shared__ float t[32][33];
    const int bx = bxi * 32, by = blockIdx.y * 32;
    const int x = bx + threadIdx.x;
#pragma unroll
    for (int i = threadIdx.y; i < 32; i += 8)
        t[i][threadIdx.x] = in[(by + i) * C + x];
    __syncthreads();
    const int xo = by + threadIdx.x;
#pragma unroll
    for (int i = threadIdx.y; i < 32; i += 8)
        out[(bx + i) * R + xo] = t[threadIdx.x][i];
}

// ---------------- bf16 helpers ----------------
__device__ __forceinline__ void split2(float x, float y, unsigned& hi, unsigned& lo) {
    __nv_bfloat16 hx = __float2bfloat16(x);
    __nv_bfloat16 hy = __float2bfloat16(y);
    __nv_bfloat16 lx = __float2bfloat16(x - __bfloat162float(hx));
    __nv_bfloat16 ly = __float2bfloat16(y - __bfloat162float(hy));
    hi = ((unsigned)__bfloat16_as_ushort(hy) << 16) | __bfloat16_as_ushort(hx);
    lo = ((unsigned)__bfloat16_as_ushort(ly) << 16) | __bfloat16_as_ushort(lx);
}
__device__ __forceinline__ unsigned packhi(float x, float y) {
    __nv_bfloat162 t = __floats2bfloat162_rn(x, y);   // .x = low half
    return *(unsigned*)&t;
}
__device__ __forceinline__ unsigned f2tf(float f) {
    unsigned u; asm("cvt.rna.tf32.f32 %0, %1;" : "=r"(u) : "f"(f)); return u;
}

__device__ __forceinline__ void mma_bf16(float* d, unsigned a0, unsigned a1,
                                         unsigned a2, unsigned a3,
                                         unsigned b0, unsigned b1) {
    asm volatile(
        "mma.sync.aligned.m16n8k16.row.col.f32.bf16.bf16.f32 "
        "{%0,%1,%2,%3}, {%4,%5,%6,%7}, {%8,%9}, {%0,%1,%2,%3};"
        : "+f"(d[0]), "+f"(d[1]), "+f"(d[2]), "+f"(d[3])
        : "r"(a0), "r"(a1), "r"(a2), "r"(a3), "r"(b0), "r"(b1));
}
__device__ __forceinline__ void mma_tf32(float* d, unsigned a0, unsigned a1,
                                         unsigned a2, unsigned a3,
                                         unsigned b0, unsigned b1) {
    asm volatile(
        "mma.sync.aligned.m16n8k8.row.col.f32.tf32.tf32.f32 "
        "{%0,%1,%2,%3}, {%4,%5,%6,%7}, {%8,%9}, {%0,%1,%2,%3};"
        : "+f"(d[0]), "+f"(d[1]), "+f"(d[2]), "+f"(d[3])
        : "r"(a0), "r"(a1), "r"(a2), "r"(a3), "r"(b0), "r"(b1));
}

// k-permutation within an 8-slice: k<4 -> 2k ; k>=4 -> 2(k-4)+1
// => fragment pair (qd, qd+4) lands at adjacent slots (2qd, 2qd+1) -> LDS.64.
__device__ __forceinline__ int kperm8(int j) {
    return (j < 4) ? (j << 1) : (((j - 4) << 1) | 1);
}

// ---------------- bf16 tensor-core GEMM (1-pass or 3-pass hi/lo) ----------------
// passes==3: Ahi*Bhi + Ahi*Blo + Alo*Bhi (rel err ~4e-6)
// passes==1: Ahi*Bhi only — for Q/K (error attenuated downstream).
#define BKC   32
#define SSTR  20

__device__ __forceinline__ void gemm_tc_body(const float* __restrict__ A,
                                             const float* __restrict__ Bt,
                                             float* __restrict__ C,
                                             int N, int K, int bx, int by,
                                             int vt, int passes,
                                             unsigned* Ahi, unsigned* Alo,
                                             unsigned* Bhi, unsigned* Blo) {
    const int tid  = threadIdx.x;
    const int lane = tid & 31;
    const int warp = tid >> 5;
    const int grp  = lane >> 2;          // 0..7
    const int qd   = lane & 3;           // 0..3
    const int wm    = (warp >> 2) << 6;  // 0 or 64
    const int wncol = (warp & 3) << 5;   // 0,32,64,96

    A  += (size_t)by * 128 * K;
    Bt += (size_t)bx * 128 * K;

    float acc[4][4][4];
#pragma unroll
    for (int i = 0; i < 4; ++i)
#pragma unroll
        for (int j = 0; j < 4; ++j)
#pragma unroll
            for (int r = 0; r < 4; ++r) acc[i][j][r] = 0.0f;

    const int ldRow = tid >> 3;          // 0..31
    const int ldT   = tid & 7;           // 0..7 -> k = 4*ldT..+3

    for (int k0 = 0; k0 < K; k0 += BKC) {
#pragma unroll
        for (int i = 0; i < 4; ++i) {
            const int row = i * 32 + ldRow;
            float4 va = *(const float4*)(A  + (size_t)row * K + k0 + ldT * 4);
            float4 vb = *(const float4*)(Bt + (size_t)row * K + k0 + ldT * 4);
            if (passes == 3) {
                unsigned h0, l0, h1, l1;
                split2(va.x, va.y, h0, l0);
                split2(va.z, va.w, h1, l1);
                Ahi[row * SSTR + ldT * 2]     = h0;
                Ahi[row * SSTR + ldT * 2 + 1] = h1;
                Alo[row * SSTR + ldT * 2]     = l0;
                Alo[row * SSTR + ldT * 2 + 1] = l1;
                split2(vb.x, vb.y, h0, l0);
                split2(vb.z, vb.w, h1, l1);
                Bhi[row * SSTR + ldT * 2]     = h0;
                Bhi[row * SSTR + ldT * 2 + 1] = h1;
                Blo[row * SSTR + ldT * 2]     = l0;
                Blo[row * SSTR + ldT * 2 + 1] = l1;
            } else {
                Ahi[row * SSTR + ldT * 2]     = packhi(va.x, va.y);
                Ahi[row * SSTR + ldT * 2 + 1] = packhi(va.z, va.w);
                Bhi[row * SSTR + ldT * 2]     = packhi(vb.x, vb.y);
                Bhi[row * SSTR + ldT * 2 + 1] = packhi(vb.z, vb.w);
            }
        }
        __syncthreads();

#pragma unroll
        for (int h = 0; h < 2; ++h) {      // two k16 steps per chunk
            unsigned ah[4][4], bh[4][2];
#pragma unroll
            for (int mt = 0; mt < 4; ++mt) {
                const int r0 = (wm + mt * 16 + grp) * SSTR + h * 8 + qd;
                const int r1 = r0 + 8 * SSTR;
                ah[mt][0] = Ahi[r0];     ah[mt][1] = Ahi[r1];
                ah[mt][2] = Ahi[r0 + 4]; ah[mt][3] = Ahi[r1 + 4];
            }
#pragma unroll
            for (int nt = 0; nt < 4; ++nt) {
                const int n0 = (wncol + nt * 8 + grp) * SSTR + h * 8 + qd;
                bh[nt][0] = Bhi[n0]; bh[nt][1] = Bhi[n0 + 4];
            }
#pragma unroll
            for (int mt = 0; mt < 4; ++mt)
#pragma unroll
                for (int nt = 0; nt < 4; ++nt)
                    mma_bf16(acc[mt][nt], ah[mt][0], ah[mt][1], ah[mt][2], ah[mt][3],
                             bh[nt][0], bh[nt][1]);
            if (passes == 3) {
                unsigned al[4][4], bl[4][2];
#pragma unroll
                for (int mt = 0; mt < 4; ++mt) {
                    const int r0 = (wm + mt * 16 + grp) * SSTR + h * 8 + qd;
                    const int r1 = r0 + 8 * SSTR;
                    al[mt][0] = Alo[r0];     al[mt][1] = Alo[r1];
                    al[mt][2] = Alo[r0 + 4]; al[mt][3] = Alo[r1 + 4];
                }
#pragma unroll
                for (int nt = 0; nt < 4; ++nt) {
                    const int n0 = (wncol + nt * 8 + grp) * SSTR + h * 8 + qd;
                    bl[nt][0] = Blo[n0]; bl[nt][1] = Blo[n0 + 4];
                }
#pragma unroll
                for (int mt = 0; mt < 4; ++mt)
#pragma unroll
                    for (int nt = 0; nt < 4; ++nt) {
                        mma_bf16(acc[mt][nt], ah[mt][0], ah[mt][1], ah[mt][2], ah[mt][3],
                                 bl[nt][0], bl[nt][1]);
                        mma_bf16(acc[mt][nt], al[mt][0], al[mt][1], al[mt][2], al[mt][3],
                                 bh[nt][0], bh[nt][1]);
                    }
            }
        }
        __syncthreads();
    }

    if (vt) {
#pragma unroll
        for (int mt = 0; mt < 4; ++mt)
#pragma unroll
            for (int nt = 0; nt < 4; ++nt) {
                const int row_g = by * 128 + wm + mt * 16 + grp;
                const int col_g = bx * 128 + wncol + nt * 8 + qd * 2;
                g_vt[(size_t)col_g       * (BATCH * S_LEN) + row_g]     = acc[mt][nt][0];
                g_vt[(size_t)(col_g + 1) * (BATCH * S_LEN) + row_g]     = acc[mt][nt][1];
                g_vt[(size_t)col_g       * (BATCH * S_LEN) + row_g + 8] = acc[mt][nt][2];
                g_vt[(size_t)(col_g + 1) * (BATCH * S_LEN) + row_g + 8] = acc[mt][nt][3];
            }
    } else {
        C += (size_t)by * 128 * N + bx * 128;
#pragma unroll
        for (int mt = 0; mt < 4; ++mt)
#pragma unroll
            for (int nt = 0; nt < 4; ++nt) {
                const int row = wm + mt * 16 + grp;
                const int col = wncol + nt * 8 + qd * 2;
                float2 lo; lo.x = acc[mt][nt][0]; lo.y = acc[mt][nt][1];
                float2 hi; hi.x = acc[mt][nt][2]; hi.y = acc[mt][nt][3];
                *(float2*)(C + (size_t)row * N + col)       = lo;
                *(float2*)(C + (size_t)(row + 8) * N + col) = hi;
            }
    }
}

// Fused QKV projection: grid.x 0..7 -> Q (1-pass), 8..9 -> K (1-pass),
//                       10..11 -> V (3-pass, transposed out)
__global__ __launch_bounds__(256) void gemm_qkv_kernel(const float* __restrict__ x) {
    __shared__ unsigned Ahi[128 * SSTR], Alo[128 * SSTR];
    __shared__ unsigned Bhi[128 * SSTR], Blo[128 * SSTR];
    const int bx = blockIdx.x, by = blockIdx.y;
    if (bx < 8)       gemm_tc_body(x, g_wqt, g_q, 1024, 1024, bx,      by, 0, 1, Ahi, Alo, Bhi, Blo);
    else if (bx < 10) gemm_tc_body(x, g_wkt, g_k, 256,  1024, bx - 8,  by, 0, 1, Ahi, Alo, Bhi, Blo);
    else              gemm_tc_body(x, g_wvt, g_vt, 256, 1024, bx - 10, by, 1, 3, Ahi, Alo, Bhi, Blo);
}

// ---------------- tf32 1-pass output GEMM ----------------
// out[4096,1024] = ctx[4096,1024] @ Wo ; tf32 m16n8k8, fp32 accum.
// SMEM rows k-permuted (kperm8) with stride 40 -> every fragment fetch is a
// conflict-free LDS.64 ((40*g + 2*qd) distinct mod 32 per half-warp).
#define TPAD 40

__global__ __launch_bounds__(256) void gemm_out_tf32_kernel(float* __restrict__ out) {
    __shared__ unsigned As[128 * TPAD];
    __shared__ unsigned Bs[128 * TPAD];
    const int tid  = threadIdx.x;
    const int lane = tid & 31;
    const int warp = tid >> 5;
    const int grp  = lane >> 2;
    const int qd   = lane & 3;
    const int wm    = (warp >> 2) << 6;
    const int wncol = (warp & 3) << 5;
    const int K = 1024, N = 1024;

    const float* A  = g_ctx + (size_t)blockIdx.y * 128 * K;
    const float* Bt = g_wot + (size_t)blockIdx.x * 128 * K;

    float acc[4][4][4];
#pragma unroll
    for (int i = 0; i < 4; ++i)
#pragma unroll
        for (int j = 0; j < 4; ++j)
#pragma unroll
            for (int r = 0; r < 4; ++r) acc[i][j][r] = 0.0f;

    const int ldRow = tid >> 3;
    const int ldT   = tid & 7;

    for (int k0 = 0; k0 < K; k0 += 32) {
#pragma unroll
        for (int i = 0; i < 4; ++i) {
            const int row = i * 32 + ldRow;
            float4 va = *(const float4*)(A  + (size_t)row * K + k0 + ldT * 4);
            float4 vb = *(const float4*)(Bt + (size_t)row * K + k0 + ldT * 4);
            // element k = 4*ldT + e ; slice s = k>>3 ; pos = s*8 + kperm8(k&7)
#pragma unroll
            for (int e = 0; e < 4; ++e) {
                const int k = 4 * ldT + e;
                const int pos = (k >> 3) * 8 + kperm8(k & 7);
                As[row * TPAD + pos] = f2tf(e == 0 ? va.x : e == 1 ? va.y : e == 2 ? va.z : va.w);
                Bs[row * TPAD + pos] = f2tf(e == 0 ? vb.x : e == 1 ? vb.y : e == 2 ? vb.z : vb.w);
            }
        }
        __syncthreads();

#pragma unroll
        for (int h = 0; h < 4; ++h) {        // four k8 steps
            unsigned af[4][4], bf[4][2];
#pragma unroll
            for (int mt = 0; mt < 4; ++mt) {
                const int base = (wm + mt * 16 + grp) * TPAD + h * 8 + 2 * qd;
                ull lo8 = *(const ull*)&As[base];
                ull hi8 = *(const ull*)&As[base + 8 * TPAD];
                af[mt][0] = (unsigned)lo8; af[mt][2] = (unsigned)(lo8 >> 32);
                af[mt][1] = (unsigned)hi8; af[mt][3] = (unsigned)(hi8 >> 32);
            }
#pragma unroll
            for (int nt = 0; nt < 4; ++nt) {
                ull bb = *(const ull*)&Bs[(wncol + nt * 8 + grp) * TPAD + h * 8 + 2 * qd];
                bf[nt][0] = (unsigned)bb; bf[nt][1] = (unsigned)(bb >> 32);
            }
#pragma unroll
            for (int mt = 0; mt < 4; ++mt)
#pragma unroll
                for (int nt = 0; nt < 4; ++nt)
                    mma_tf32(acc[mt][nt], af[mt][0], af[mt][1], af[mt][2], af[mt][3],
                             bf[nt][0], bf[nt][1]);
        }
        __syncthreads();
    }

    float* Cp = out + (size_t)blockIdx.y * 128 * N + blockIdx.x * 128;
#pragma unroll
    for (int mt = 0; mt < 4; ++mt)
#pragma unroll
        for (int nt = 0; nt < 4; ++nt) {
            const int row = wm + mt * 16 + grp;
            const int col = wncol + nt * 8 + qd * 2;
            float2 lo; lo.x = acc[mt][nt][0]; lo.y = acc[mt][nt][1];
            float2 hi; hi.x = acc[mt][nt][2]; hi.y = acc[mt][nt][3];
            *(float2*)(Cp + (size_t)row * N + col)       = lo;
            *(float2*)(Cp + (size_t)(row + 8) * N + col) = hi;
        }
}

// ---------------- L2 normalize + RoPE (warp per token-head; Q and K only) ------
__global__ void normrope_kernel(const float* __restrict__ cosv,
                                const float* __restrict__ sinv) {
    const int gw   = (blockIdx.x * blockDim.x + threadIdx.x) >> 5;
    const int lane = threadIdx.x & 31;
    const int NQ   = BATCH * S_LEN * NH;
    const int NTOT = NQ + BATCH * S_LEN * NKV;
    if (gw >= NTOT) return;
    float* base;
    int tok;
    if (gw < NQ) { base = g_q + gw * DH; tok = gw / NH; }
    else         { int g2 = gw - NQ; base = g_k + g2 * DH; tok = g2 / NKV; }
    const int s = tok & (S_LEN - 1);

    float x1 = base[lane];
    float x2 = base[lane + 32];
    float ss = x1 * x1 + x2 * x2;
#pragma unroll
    for (int o = 16; o; o >>= 1) ss += __shfl_xor_sync(0xffffffffu, ss, o);
    const float inv = 1.0f / (sqrtf(ss) + 1e-8f);
    x1 *= inv; x2 *= inv;
    const float c  = cosv[s * 32 + lane];
    const float sn = sinv[s * 32 + lane];
    base[lane]      = x1 * c - x2 * sn;
    base[lane + 32] = x1 * sn + x2 * c;
}

// ---------------- Tensor-core attention (2 heads of a KV group per block) ------
// 256 threads = 8 warps. K/V SMEM rows k-permuted (kperm8), stride 40:
// fragment pair (qd, qd+4) adjacent -> LDS.64, conflict-free per half-warp.
// S = Q K^T: 1-pass bf16. PV: 3-pass hi/lo.
#define KSTR 40

__global__ __launch_bounds__(256, 2) void attn_tc_kernel() {
    __shared__ unsigned Khi[64 * KSTR];
    __shared__ unsigned Vthi[64 * KSTR], Vtlo[64 * KSTR];
    const int tid  = threadIdx.x;
    const int lane = tid & 31;
    const int w    = tid >> 5;       // 0..7
    const int g    = lane >> 2;
    const int qd   = lane & 3;
    const int wq   = w & 3;          // q-row group within tile
    const int hs   = w >> 2;         // head slot (0..1)
    const int by   = blockIdx.y;     // 0..15
    const int b    = by >> 3;
    const int kh   = (by >> 1) & 3;
    const int hp   = by & 1;
    const int h    = (kh << 2) + (hp << 1) + hs;
    const int qb   = blockIdx.x << 6;        // 64-query tile base
    const int qrow = qb + (wq << 4) + g;     // rows qrow and qrow+8

    // Q A-fragments (hi only) for 4 k-steps over dh
    unsigned qhf[4][4];
    {
        const float* Qb = g_q + ((size_t)(b * S_LEN + qb + (wq << 4)) * NH + h) * DH;
#pragma unroll
        for (int s = 0; s < 4; ++s) {
            float2 f0 = *(const float2*)(Qb + g * 1024 + s * 16 + 2 * qd);
            float2 f1 = *(const float2*)(Qb + (g + 8) * 1024 + s * 16 + 2 * qd);
            float2 f2 = *(const float2*)(Qb + g * 1024 + s * 16 + 8 + 2 * qd);
            float2 f3 = *(const float2*)(Qb + (g + 8) * 1024 + s * 16 + 8 + 2 * qd);
            qhf[s][0] = packhi(f0.x, f0.y);
            qhf[s][1] = packhi(f1.x, f1.y);
            qhf[s][2] = packhi(f2.x, f2.y);
            qhf[s][3] = packhi(f3.x, f3.y);
        }
    }

    float oacc[8][4];
#pragma unroll
    for (int i = 0; i < 8; ++i)
#pragma unroll
        for (int j = 0; j < 4; ++j) oacc[i][j] = 0.0f;
    float lsum0 = 0.0f, lsum1 = 0.0f;

    const int lo_chunk = (qb > (WINDOW - 1)) ? ((qb - (WINDOW - 1)) >> 6) : 0;
    const int hi_chunk = qb >> 6;

    for (int c = 0; c <= hi_chunk; ++c) {
        if (c > 0 && c < lo_chunk) continue;   // uniform across block
        // stage K chunk (hi only) and V chunk (hi/lo), k-permuted layout
        {
            const float* Kb = g_k + ((size_t)(b * S_LEN + (c << 6)) * NKV + kh) * DH;
#pragma unroll
            for (int r = 0; r < 4; ++r) {
                const int idx = (r << 8) + tid;          // 0..1023
                const int row = idx >> 4, c4 = idx & 15;
                const int u0 = 2 * c4, u1 = 2 * c4 + 1;
                const int p0 = (u0 >> 3) * 8 + kperm8(u0 & 7);
                const int p1 = (u1 >> 3) * 8 + kperm8(u1 & 7);
                float4 v = *(const float4*)(Kb + (size_t)row * (NKV * DH) + c4 * 4);
                Khi[row * KSTR + p0] = packhi(v.x, v.y);
                Khi[row * KSTR + p1] = packhi(v.z, v.w);
            }
            const float* Vb = g_vt + (size_t)(kh * DH) * (BATCH * S_LEN)
                            + b * S_LEN + (c << 6);
#pragma unroll
            for (int r = 0; r < 4; ++r) {
                const int idx = (r << 8) + tid;
                const int row = idx >> 4, c4 = idx & 15;     // row = dh
                const int u0 = 2 * c4, u1 = 2 * c4 + 1;
                const int p0 = (u0 >> 3) * 8 + kperm8(u0 & 7);
                const int p1 = (u1 >> 3) * 8 + kperm8(u1 & 7);
                float4 v = *(const float4*)(Vb + (size_t)row * (BATCH * S_LEN) + c4 * 4);
                unsigned h0, l0, h1, l1;
                split2(v.x, v.y, h0, l0);
                split2(v.z, v.w, h1, l1);
                Vthi[row * KSTR + p0] = h0;
                Vthi[row * KSTR + p1] = h1;
                Vtlo[row * KSTR + p0] = l0;
                Vtlo[row * KSTR + p1] = l1;
            }
        }
        __syncthreads();

        // S = Q K^T  (1-pass bf16; warp: 16 q-rows x 64 keys)
        float sacc[8][4];
#pragma unroll
        for (int i = 0; i < 8; ++i)
#pragma unroll
            for (int j = 0; j < 4; ++j) sacc[i][j] = 0.0f;
#pragma unroll
        for (int s = 0; s < 4; ++s) {
#pragma unroll
            for (int nt = 0; nt < 8; ++nt) {
                const int n0 = (nt * 8 + g) * KSTR + s * 8 + 2 * qd;
                ull kk = *(const ull*)&Khi[n0];
                mma_bf16(sacc[nt], qhf[s][0], qhf[s][1], qhf[s][2], qhf[s][3],
                         (unsigned)kk, (unsigned)(kk >> 32));
            }
        }

        // softcap + mask + exp in fragments, pack P hi/lo
        unsigned phi[8][2], plo[8][2];
#pragma unroll
        for (int nt = 0; nt < 8; ++nt) {
            float p[4];
#pragma unroll
            for (int e = 0; e < 4; ++e) {
                const int key = (c << 6) + nt * 8 + 2 * qd + (e & 1);
                const int qg  = (e < 2) ? qrow : (qrow + 8);
                const float sv  = sacc[nt][e];
                const float scx = sv * 0.125f;
                const float cap = scx - scx * scx * scx * (1.0f / 675.0f);
                const bool valid = (key <= qg) && ((key > qg - WINDOW) || (key < NGLOB));
                p[e] = valid ? __expf(cap) : 0.0f;
            }
            lsum0 += p[0] + p[1];
            lsum1 += p[2] + p[3];
            split2(p[0], p[1], phi[nt][0], plo[nt][0]);
            split2(p[2], p[3], phi[nt][1], plo[nt][1]);
        }

        // O += P V   (A-fragments = S C-fragments, FA2 identity; 3-pass)
#pragma unroll
        for (int s = 0; s < 4; ++s) {
            const unsigned a0h = phi[2 * s][0],     a1h = phi[2 * s][1];
            const unsigned a2h = phi[2 * s + 1][0], a3h = phi[2 * s + 1][1];
            const unsigned a0l = plo[2 * s][0],     a1l = plo[2 * s][1];
            const unsigned a2l = plo[2 * s + 1][0], a3l = plo[2 * s + 1][1];
#pragma unroll
            for (int nt = 0; nt < 8; ++nt) {
                const int n0 = (nt * 8 + g) * KSTR + s * 8 + 2 * qd;
                ull vh = *(const ull*)&Vthi[n0];
                ull vl = *(const ull*)&Vtlo[n0];
                const unsigned vb0 = (unsigned)vh, vb1 = (unsigned)(vh >> 32);
                const unsigned vl0 = (unsigned)vl, vl1 = (unsigned)(vl >> 32);
                mma_bf16(oacc[nt], a0h, a1h, a2h, a3h, vb0, vb1);
                mma_bf16(oacc[nt], a0h, a1h, a2h, a3h, vl0, vl1);
                mma_bf16(oacc[nt], a0l, a1l, a2l, a3l, vb0, vb1);
            }
        }
        __syncthreads();
    }

    // reduce l across the 4 qd lanes (lane = 4*g + qd)
    lsum0 += __shfl_xor_sync(0xffffffffu, lsum0, 1);
    lsum0 += __shfl_xor_sync(0xffffffffu, lsum0, 2);
    lsum1 += __shfl_xor_sync(0xffffffffu, lsum1, 1);
    lsum1 += __shfl_xor_sync(0xffffffffu, lsum1, 2);
    const float i0 = 1.0f / lsum0;
    const float i1 = 1.0f / lsum1;

    float* Ob = g_ctx + ((size_t)(b * S_LEN + qrow) * NH + h) * DH;
#pragma unroll
    for (int nt = 0; nt < 8; ++nt) {
        float2 v0; v0.x = oacc[nt][0] * i0; v0.y = oacc[nt][1] * i0;
        float2 v1; v1.x = oacc[nt][2] * i1; v1.y = oacc[nt][3] * i1;
        *(float2*)(Ob + nt * 8 + 2 * qd) = v0;
        *(float2*)(Ob + 8 * NH * DH + nt * 8 + 2 * qd) = v1;   // row qrow+8
    }
}

// ---------------- launch ----------------
extern "C" void kernel_launch(void* const* d_in, const int* in_sizes, int n_in,
                              void* d_out, int out_size) {
    const float* x    = (const float*)d_in[0];
    const float* cosv = (const float*)d_in[1];
    const float* sinv = (const float*)d_in[2];
    // d_in[3] = mask (bool) — recomputed analytically
    const float* Wq   = (const float*)d_in[4];
    const float* Wk   = (const float*)d_in[5];
    const float* Wv   = (const float*)d_in[6];
    const float* Wo   = (const float*)d_in[7];
    float* out = (float*)d_out;

    tr_all_kernel<<<dim3(80, 32), dim3(32, 8)>>>(Wq, Wk, Wv, Wo);

    gemm_qkv_kernel<<<dim3(12, 32), 256>>>(x);

    const int nwarps  = BATCH * S_LEN * (NH + NKV);      // 81920
    const int nthread = nwarps * 32;
    normrope_kernel<<<(nthread + 255) / 256, 256>>>(cosv, sinv);

    attn_tc_kernel<<<dim3(S_LEN / 64, BATCH * NKV * 2), 256>>>();

    gemm_out_tf32_kernel<<<dim3(DMODEL / 128, (BATCH * S_LEN) / 128), 256>>>(out);
}

// round 16
// speedup vs baseline: 3.4880x; 1.1134x over previous
#include <cuda_runtime.h>
#include <cuda_bf16.h>

#define S_LEN   2048
#define BATCH   2
#define NH      16
#define NKV     4
#define DH      64
#define DMODEL  1024
#define WINDOW  256
#define NGLOB   4

typedef unsigned long long ull;

// Scratch buffers (allocation-free rule: __device__ globals)
__device__ float g_q[BATCH * S_LEN * NH * DH];        // [tok,16,64]
__device__ float g_k[BATCH * S_LEN * NKV * DH];       // [tok,4,64]
__device__ float g_vt[NKV * DH * BATCH * S_LEN];      // TRANSPOSED V: [kvh*64+dh][tok]
__device__ float g_ctx[BATCH * S_LEN * NH * DH];      // [tok,1024]
// Transposed weights (B^T, row-major [N][K]) for mma.sync row.col
__device__ float g_wqt[1024 * 1024];
__device__ float g_wkt[256 * 1024];
__device__ float g_wvt[256 * 1024];
__device__ float g_wot[1024 * 1024];

// ---------------- merged weight transpose (one launch) ----------------
__global__ __launch_bounds__(256) void tr_all_kernel(const float* __restrict__ Wq,
                                                     const float* __restrict__ Wk,
                                                     const float* __restrict__ Wv,
                                                     const float* __restrict__ Wo) {
    int bxi = blockIdx.x;
    const float* in; float* out; int C;
    if (bxi < 32)      { in = Wq; out = g_wqt; C = 1024; }
    else if (bxi < 40) { in = Wk; out = g_wkt; C = 256;  bxi -= 32; }
    else if (bxi < 48) { in = Wv; out = g_wvt; C = 256;  bxi -= 40; }
    else               { in = Wo; out = g_wot; C = 1024; bxi -= 48; }
    const int R = 1024;
    __shared__ float t[32][33];
    const int bx = bxi * 32, by = blockIdx.y * 32;
    const int x = bx + threadIdx.x;
#pragma unroll
    for (int i = threadIdx.y; i < 32; i += 8)
        t[i][threadIdx.x] = in[(by + i) * C + x];
    __syncthreads();
    const int xo = by + threadIdx.x;
#pragma unroll
    for (int i = threadIdx.y; i < 32; i += 8)
        out[(bx + i) * R + xo] = t[threadIdx.x][i];
}

// ---------------- bf16 helpers ----------------
__device__ __forceinline__ void split2(float x, float y, unsigned& hi, unsigned& lo) {
    __nv_bfloat16 hx = __float2bfloat16(x);
    __nv_bfloat16 hy = __float2bfloat16(y);
    __nv_bfloat16 lx = __float2bfloat16(x - __bfloat162float(hx));
    __nv_bfloat16 ly = __float2bfloat16(y - __bfloat162float(hy));
    hi = ((unsigned)__bfloat16_as_ushort(hy) << 16) | __bfloat16_as_ushort(hx);
    lo = ((unsigned)__bfloat16_as_ushort(ly) << 16) | __bfloat16_as_ushort(lx);
}
__device__ __forceinline__ unsigned packhi(float x, float y) {
    __nv_bfloat162 t = __floats2bfloat162_rn(x, y);   // .x = low half
    return *(unsigned*)&t;
}
__device__ __forceinline__ unsigned f2tf(float f) {
    unsigned u; asm("cvt.rna.tf32.f32 %0, %1;" : "=r"(u) : "f"(f)); return u;
}

__device__ __forceinline__ void mma_bf16(float* d, unsigned a0, unsigned a1,
                                         unsigned a2, unsigned a3,
                                         unsigned b0, unsigned b1) {
    asm volatile(
        "mma.sync.aligned.m16n8k16.row.col.f32.bf16.bf16.f32 "
        "{%0,%1,%2,%3}, {%4,%5,%6,%7}, {%8,%9}, {%0,%1,%2,%3};"
        : "+f"(d[0]), "+f"(d[1]), "+f"(d[2]), "+f"(d[3])
        : "r"(a0), "r"(a1), "r"(a2), "r"(a3), "r"(b0), "r"(b1));
}
__device__ __forceinline__ void mma_tf32(float* d, unsigned a0, unsigned a1,
                                         unsigned a2, unsigned a3,
                                         unsigned b0, unsigned b1) {
    asm volatile(
        "mma.sync.aligned.m16n8k8.row.col.f32.tf32.tf32.f32 "
        "{%0,%1,%2,%3}, {%4,%5,%6,%7}, {%8,%9}, {%0,%1,%2,%3};"
        : "+f"(d[0]), "+f"(d[1]), "+f"(d[2]), "+f"(d[3])
        : "r"(a0), "r"(a1), "r"(a2), "r"(a3), "r"(b0), "r"(b1));
}

// ---------------- bf16 tensor-core GEMM (1-pass or 3-pass hi/lo) ----------------
// passes==3: Ahi*Bhi + Ahi*Blo + Alo*Bhi (rel err ~4e-6)
// passes==1: Ahi*Bhi only — for Q/K (error attenuated downstream).
#define BKC   32
#define SSTR  20

__device__ __forceinline__ void gemm_tc_body(const float* __restrict__ A,
                                             const float* __restrict__ Bt,
                                             float* __restrict__ C,
                                             int N, int K, int bx, int by,
                                             int vt, int passes,
                                             unsigned* Ahi, unsigned* Alo,
                                             unsigned* Bhi, unsigned* Blo) {
    const int tid  = threadIdx.x;
    const int lane = tid & 31;
    const int warp = tid >> 5;
    const int grp  = lane >> 2;          // 0..7
    const int qd   = lane & 3;           // 0..3
    const int wm    = (warp >> 2) << 6;  // 0 or 64
    const int wncol = (warp & 3) << 5;   // 0,32,64,96

    A  += (size_t)by * 128 * K;
    Bt += (size_t)bx * 128 * K;

    float acc[4][4][4];
#pragma unroll
    for (int i = 0; i < 4; ++i)
#pragma unroll
        for (int j = 0; j < 4; ++j)
#pragma unroll
            for (int r = 0; r < 4; ++r) acc[i][j][r] = 0.0f;

    const int ldRow = tid >> 3;          // 0..31
    const int ldT   = tid & 7;           // 0..7 -> k = 4*ldT..+3

    for (int k0 = 0; k0 < K; k0 += BKC) {
#pragma unroll
        for (int i = 0; i < 4; ++i) {
            const int row = i * 32 + ldRow;
            float4 va = *(const float4*)(A  + (size_t)row * K + k0 + ldT * 4);
            float4 vb = *(const float4*)(Bt + (size_t)row * K + k0 + ldT * 4);
            if (passes == 3) {
                unsigned h0, l0, h1, l1;
                split2(va.x, va.y, h0, l0);
                split2(va.z, va.w, h1, l1);
                Ahi[row * SSTR + ldT * 2]     = h0;
                Ahi[row * SSTR + ldT * 2 + 1] = h1;
                Alo[row * SSTR + ldT * 2]     = l0;
                Alo[row * SSTR + ldT * 2 + 1] = l1;
                split2(vb.x, vb.y, h0, l0);
                split2(vb.z, vb.w, h1, l1);
                Bhi[row * SSTR + ldT * 2]     = h0;
                Bhi[row * SSTR + ldT * 2 + 1] = h1;
                Blo[row * SSTR + ldT * 2]     = l0;
                Blo[row * SSTR + ldT * 2 + 1] = l1;
            } else {
                Ahi[row * SSTR + ldT * 2]     = packhi(va.x, va.y);
                Ahi[row * SSTR + ldT * 2 + 1] = packhi(va.z, va.w);
                Bhi[row * SSTR + ldT * 2]     = packhi(vb.x, vb.y);
                Bhi[row * SSTR + ldT * 2 + 1] = packhi(vb.z, vb.w);
            }
        }
        __syncthreads();

#pragma unroll
        for (int h = 0; h < 2; ++h) {      // two k16 steps per chunk
            unsigned ah[4][4], bh[4][2];
#pragma unroll
            for (int mt = 0; mt < 4; ++mt) {
                const int r0 = (wm + mt * 16 + grp) * SSTR + h * 8 + qd;
                const int r1 = r0 + 8 * SSTR;
                ah[mt][0] = Ahi[r0];     ah[mt][1] = Ahi[r1];
                ah[mt][2] = Ahi[r0 + 4]; ah[mt][3] = Ahi[r1 + 4];
            }
#pragma unroll
            for (int nt = 0; nt < 4; ++nt) {
                const int n0 = (wncol + nt * 8 + grp) * SSTR + h * 8 + qd;
                bh[nt][0] = Bhi[n0]; bh[nt][1] = Bhi[n0 + 4];
            }
#pragma unroll
            for (int mt = 0; mt < 4; ++mt)
#pragma unroll
                for (int nt = 0; nt < 4; ++nt)
                    mma_bf16(acc[mt][nt], ah[mt][0], ah[mt][1], ah[mt][2], ah[mt][3],
                             bh[nt][0], bh[nt][1]);
            if (passes == 3) {
                unsigned al[4][4], bl[4][2];
#pragma unroll
                for (int mt = 0; mt < 4; ++mt) {
                    const int r0 = (wm + mt * 16 + grp) * SSTR + h * 8 + qd;
                    const int r1 = r0 + 8 * SSTR;
                    al[mt][0] = Alo[r0];     al[mt][1] = Alo[r1];
                    al[mt][2] = Alo[r0 + 4]; al[mt][3] = Alo[r1 + 4];
                }
#pragma unroll
                for (int nt = 0; nt < 4; ++nt) {
                    const int n0 = (wncol + nt * 8 + grp) * SSTR + h * 8 + qd;
                    bl[nt][0] = Blo[n0]; bl[nt][1] = Blo[n0 + 4];
                }
#pragma unroll
                for (int mt = 0; mt < 4; ++mt)
#pragma unroll
                    for (int nt = 0; nt < 4; ++nt) {
                        mma_bf16(acc[mt][nt], ah[mt][0], ah[mt][1], ah[mt][2], ah[mt][3],
                                 bl[nt][0], bl[nt][1]);
                        mma_bf16(acc[mt][nt], al[mt][0], al[mt][1], al[mt][2], al[mt][3],
                                 bh[nt][0], bh[nt][1]);
                    }
            }
        }
        __syncthreads();
    }

    if (vt) {
#pragma unroll
        for (int mt = 0; mt < 4; ++mt)
#pragma unroll
            for (int nt = 0; nt < 4; ++nt) {
                const int row_g = by * 128 + wm + mt * 16 + grp;
                const int col_g = bx * 128 + wncol + nt * 8 + qd * 2;
                g_vt[(size_t)col_g       * (BATCH * S_LEN) + row_g]     = acc[mt][nt][0];
                g_vt[(size_t)(col_g + 1) * (BATCH * S_LEN) + row_g]     = acc[mt][nt][1];
                g_vt[(size_t)col_g       * (BATCH * S_LEN) + row_g + 8] = acc[mt][nt][2];
                g_vt[(size_t)(col_g + 1) * (BATCH * S_LEN) + row_g + 8] = acc[mt][nt][3];
            }
    } else {
        C += (size_t)by * 128 * N + bx * 128;
#pragma unroll
        for (int mt = 0; mt < 4; ++mt)
#pragma unroll
            for (int nt = 0; nt < 4; ++nt) {
                const int row = wm + mt * 16 + grp;
                const int col = wncol + nt * 8 + qd * 2;
                float2 lo; lo.x = acc[mt][nt][0]; lo.y = acc[mt][nt][1];
                float2 hi; hi.x = acc[mt][nt][2]; hi.y = acc[mt][nt][3];
                *(float2*)(C + (size_t)row * N + col)       = lo;
                *(float2*)(C + (size_t)(row + 8) * N + col) = hi;
            }
    }
}

// Fused QKV projection: grid.x 0..7 -> Q (1-pass), 8..9 -> K (1-pass),
//                       10..11 -> V (3-pass, transposed out)
__global__ __launch_bounds__(256) void gemm_qkv_kernel(const float* __restrict__ x) {
    __shared__ unsigned Ahi[128 * SSTR], Alo[128 * SSTR];
    __shared__ unsigned Bhi[128 * SSTR], Blo[128 * SSTR];
    const int bx = blockIdx.x, by = blockIdx.y;
    if (bx < 8)       gemm_tc_body(x, g_wqt, g_q, 1024, 1024, bx,      by, 0, 1, Ahi, Alo, Bhi, Blo);
    else if (bx < 10) gemm_tc_body(x, g_wkt, g_k, 256,  1024, bx - 8,  by, 0, 1, Ahi, Alo, Bhi, Blo);
    else              gemm_tc_body(x, g_wvt, g_vt, 256, 1024, bx - 10, by, 1, 3, Ahi, Alo, Bhi, Blo);
}

// ---------------- tf32 1-pass output GEMM (vectorized staging) ----------------
// Linear SMEM rows, stride 36: fragment fetch addr (36*g + qd) mod 32 = 4g+qd
// -> all 32 distinct -> conflict-free LDS.32. Staging is one STS.128 per
// float4 (16B-aligned; banks 4t..4t+3 over 8 ldT cover all 32 once).
#define TSTR 36

__global__ __launch_bounds__(256) void gemm_out_tf32_kernel(float* __restrict__ out) {
    __shared__ __align__(16) unsigned As[128 * TSTR];
    __shared__ __align__(16) unsigned Bs[128 * TSTR];
    const int tid  = threadIdx.x;
    const int lane = tid & 31;
    const int warp = tid >> 5;
    const int grp  = lane >> 2;
    const int qd   = lane & 3;
    const int wm    = (warp >> 2) << 6;
    const int wncol = (warp & 3) << 5;
    const int K = 1024, N = 1024;

    const float* A  = g_ctx + (size_t)blockIdx.y * 128 * K;
    const float* Bt = g_wot + (size_t)blockIdx.x * 128 * K;

    float acc[4][4][4];
#pragma unroll
    for (int i = 0; i < 4; ++i)
#pragma unroll
        for (int j = 0; j < 4; ++j)
#pragma unroll
            for (int r = 0; r < 4; ++r) acc[i][j][r] = 0.0f;

    const int ldRow = tid >> 3;
    const int ldT4  = (tid & 7) * 4;

    for (int k0 = 0; k0 < K; k0 += 32) {
#pragma unroll
        for (int i = 0; i < 4; ++i) {
            const int row = i * 32 + ldRow;
            float4 va = *(const float4*)(A  + (size_t)row * K + k0 + ldT4);
            float4 vb = *(const float4*)(Bt + (size_t)row * K + k0 + ldT4);
            uint4 ua; ua.x = f2tf(va.x); ua.y = f2tf(va.y); ua.z = f2tf(va.z); ua.w = f2tf(va.w);
            uint4 ub; ub.x = f2tf(vb.x); ub.y = f2tf(vb.y); ub.z = f2tf(vb.z); ub.w = f2tf(vb.w);
            *(uint4*)&As[row * TSTR + ldT4] = ua;
            *(uint4*)&Bs[row * TSTR + ldT4] = ub;
        }
        __syncthreads();

#pragma unroll
        for (int h = 0; h < 4; ++h) {        // four k8 steps
            unsigned af[4][4], bf[4][2];
#pragma unroll
            for (int mt = 0; mt < 4; ++mt) {
                const int base = (wm + mt * 16 + grp) * TSTR + h * 8 + qd;
                af[mt][0] = As[base];
                af[mt][2] = As[base + 4];
                af[mt][1] = As[base + 8 * TSTR];
                af[mt][3] = As[base + 8 * TSTR + 4];
            }
#pragma unroll
            for (int nt = 0; nt < 4; ++nt) {
                const int bb = (wncol + nt * 8 + grp) * TSTR + h * 8 + qd;
                bf[nt][0] = Bs[bb]; bf[nt][1] = Bs[bb + 4];
            }
#pragma unroll
            for (int mt = 0; mt < 4; ++mt)
#pragma unroll
                for (int nt = 0; nt < 4; ++nt)
                    mma_tf32(acc[mt][nt], af[mt][0], af[mt][1], af[mt][2], af[mt][3],
                             bf[nt][0], bf[nt][1]);
        }
        __syncthreads();
    }

    float* Cp = out + (size_t)blockIdx.y * 128 * N + blockIdx.x * 128;
#pragma unroll
    for (int mt = 0; mt < 4; ++mt)
#pragma unroll
        for (int nt = 0; nt < 4; ++nt) {
            const int row = wm + mt * 16 + grp;
            const int col = wncol + nt * 8 + qd * 2;
            float2 lo; lo.x = acc[mt][nt][0]; lo.y = acc[mt][nt][1];
            float2 hi; hi.x = acc[mt][nt][2]; hi.y = acc[mt][nt][3];
            *(float2*)(Cp + (size_t)row * N + col)       = lo;
            *(float2*)(Cp + (size_t)(row + 8) * N + col) = hi;
        }
}

// ---------------- L2 normalize + RoPE (warp per token-head; Q and K only) ------
__global__ void normrope_kernel(const float* __restrict__ cosv,
                                const float* __restrict__ sinv) {
    const int gw   = (blockIdx.x * blockDim.x + threadIdx.x) >> 5;
    const int lane = threadIdx.x & 31;
    const int NQ   = BATCH * S_LEN * NH;
    const int NTOT = NQ + BATCH * S_LEN * NKV;
    if (gw >= NTOT) return;
    float* base;
    int tok;
    if (gw < NQ) { base = g_q + gw * DH; tok = gw / NH; }
    else         { int g2 = gw - NQ; base = g_k + g2 * DH; tok = g2 / NKV; }
    const int s = tok & (S_LEN - 1);

    float x1 = base[lane];
    float x2 = base[lane + 32];
    float ss = x1 * x1 + x2 * x2;
#pragma unroll
    for (int o = 16; o; o >>= 1) ss += __shfl_xor_sync(0xffffffffu, ss, o);
    const float inv = 1.0f / (sqrtf(ss) + 1e-8f);
    x1 *= inv; x2 *= inv;
    const float c  = cosv[s * 32 + lane];
    const float sn = sinv[s * 32 + lane];
    base[lane]      = x1 * c - x2 * sn;
    base[lane + 32] = x1 * sn + x2 * c;
}

// ---------------- Tensor-core attention (2 heads of a KV group per block) ------
// 256 threads = 8 warps. Linear KSTR=36 layout (round-9 proven).
// S = Q K^T: 1-pass bf16. PV: 3-pass hi/lo.
// Global-chunk fast path: only keys 0..3 valid; b1 passed as 0 (keys 8..15
// NEVER read from unstaged SMEM — 0 x NaN poisoning was the round-15 bug).
#define KSTR 36

__global__ __launch_bounds__(256, 2) void attn_tc_kernel() {
    __shared__ unsigned Khi[64 * KSTR];
    __shared__ unsigned Vthi[64 * KSTR], Vtlo[64 * KSTR];
    const int tid  = threadIdx.x;
    const int lane = tid & 31;
    const int w    = tid >> 5;       // 0..7
    const int g    = lane >> 2;
    const int qd   = lane & 3;
    const int wq   = w & 3;          // q-row group within tile
    const int hs   = w >> 2;         // head slot (0..1)
    const int by   = blockIdx.y;     // 0..15
    const int b    = by >> 3;
    const int kh   = (by >> 1) & 3;
    const int hp   = by & 1;
    const int h    = (kh << 2) + (hp << 1) + hs;
    const int qb   = blockIdx.x << 6;        // 64-query tile base
    const int qrow = qb + (wq << 4) + g;     // rows qrow and qrow+8

    // Q A-fragments (hi only) for 4 k-steps over dh
    unsigned qhf[4][4];
    {
        const float* Qb = g_q + ((size_t)(b * S_LEN + qb + (wq << 4)) * NH + h) * DH;
#pragma unroll
        for (int s = 0; s < 4; ++s) {
            float2 f0 = *(const float2*)(Qb + g * 1024 + s * 16 + 2 * qd);
            float2 f1 = *(const float2*)(Qb + (g + 8) * 1024 + s * 16 + 2 * qd);
            float2 f2 = *(const float2*)(Qb + g * 1024 + s * 16 + 8 + 2 * qd);
            float2 f3 = *(const float2*)(Qb + (g + 8) * 1024 + s * 16 + 8 + 2 * qd);
            qhf[s][0] = packhi(f0.x, f0.y);
            qhf[s][1] = packhi(f1.x, f1.y);
            qhf[s][2] = packhi(f2.x, f2.y);
            qhf[s][3] = packhi(f3.x, f3.y);
        }
    }

    float oacc[8][4];
#pragma unroll
    for (int i = 0; i < 8; ++i)
#pragma unroll
        for (int j = 0; j < 4; ++j) oacc[i][j] = 0.0f;
    float lsum0 = 0.0f, lsum1 = 0.0f;

    const int lo_chunk = (qb > (WINDOW - 1)) ? ((qb - (WINDOW - 1)) >> 6) : 0;
    const int hi_chunk = qb >> 6;

    int c_start = 0;
    if (lo_chunk > 0) {
        // ---- global fast chunk (c = 0): only keys 0..3 can be valid ----
        {
            const float* Kb = g_k + ((size_t)(b * S_LEN) * NKV + kh) * DH;
            const float* Vb = g_vt + (size_t)(kh * DH) * (BATCH * S_LEN) + b * S_LEN;
            if (tid < 128) {                  // K rows (keys) 0..7, full dh
                const int row = tid >> 4, c4 = tid & 15;
                float4 v = *(const float4*)(Kb + (size_t)row * (NKV * DH) + c4 * 4);
                Khi[row * KSTR + c4 * 2]     = packhi(v.x, v.y);
                Khi[row * KSTR + c4 * 2 + 1] = packhi(v.z, v.w);
            } else {                          // V all dh rows, keys 0..7
                const int t = tid - 128;      // 0..127
                const int row = t >> 1, c4 = t & 1;
                float4 v = *(const float4*)(Vb + (size_t)row * (BATCH * S_LEN) + c4 * 4);
                unsigned h0, l0, h1, l1;
                split2(v.x, v.y, h0, l0);
                split2(v.z, v.w, h1, l1);
                Vthi[row * KSTR + c4 * 2]     = h0;
                Vthi[row * KSTR + c4 * 2 + 1] = h1;
                Vtlo[row * KSTR + c4 * 2]     = l0;
                Vtlo[row * KSTR + c4 * 2 + 1] = l1;
            }
        }
        __syncthreads();

        // S for keys 0..7 only (nt = 0); K dh-pairs fully staged
        float sacc0[4] = {0.f, 0.f, 0.f, 0.f};
#pragma unroll
        for (int s = 0; s < 4; ++s) {
            const int n0 = g * KSTR + s * 8 + qd;
            mma_bf16(sacc0, qhf[s][0], qhf[s][1], qhf[s][2], qhf[s][3],
                     Khi[n0], Khi[n0 + 4]);
        }
        // keys 2qd + (e&1); valid iff key < NGLOB (causal always true here)
        float p[4];
#pragma unroll
        for (int e = 0; e < 4; ++e) {
            const float scx = sacc0[e] * 0.125f;
            const float cap = scx - scx * scx * scx * (1.0f / 675.0f);
            p[e] = (qd < 2) ? __expf(cap) : 0.0f;
        }
        lsum0 += p[0] + p[1];
        lsum1 += p[2] + p[3];
        unsigned ph0, pl0, ph1, pl1;
        split2(p[0], p[1], ph0, pl0);
        split2(p[2], p[3], ph1, pl1);
        // PV: s=0 only; keys 8..15 half contributes 0 via a2=a3=0 AND b1=0
        // (b1 must be literal 0 — SMEM pairs 4..7 are unstaged here).
#pragma unroll
        for (int nt = 0; nt < 8; ++nt) {
            const int n0 = (nt * 8 + g) * KSTR + qd;
            unsigned vb0 = Vthi[n0];
            unsigned vl0 = Vtlo[n0];
            mma_bf16(oacc[nt], ph0, ph1, 0u, 0u, vb0, 0u);
            mma_bf16(oacc[nt], ph0, ph1, 0u, 0u, vl0, 0u);
            mma_bf16(oacc[nt], pl0, pl1, 0u, 0u, vb0, 0u);
        }
        __syncthreads();
        c_start = lo_chunk;
    }

    for (int c = c_start; c <= hi_chunk; ++c) {
        // stage K chunk (hi only) and V chunk (hi/lo) — shared by both heads
        {
            const float* Kb = g_k + ((size_t)(b * S_LEN + (c << 6)) * NKV + kh) * DH;
#pragma unroll
            for (int r = 0; r < 4; ++r) {
                const int idx = (r << 8) + tid;          // 0..1023
                const int row = idx >> 4, c4 = idx & 15;
                float4 v = *(const float4*)(Kb + (size_t)row * (NKV * DH) + c4 * 4);
                Khi[row * KSTR + c4 * 2]     = packhi(v.x, v.y);
                Khi[row * KSTR + c4 * 2 + 1] = packhi(v.z, v.w);
            }
            const float* Vb = g_vt + (size_t)(kh * DH) * (BATCH * S_LEN)
                            + b * S_LEN + (c << 6);
#pragma unroll
            for (int r = 0; r < 4; ++r) {
                const int idx = (r << 8) + tid;
                const int row = idx >> 4, c4 = idx & 15;     // row = dh
                float4 v = *(const float4*)(Vb + (size_t)row * (BATCH * S_LEN) + c4 * 4);
                unsigned h0, l0, h1, l1;
                split2(v.x, v.y, h0, l0);
                split2(v.z, v.w, h1, l1);
                Vthi[row * KSTR + c4 * 2]     = h0;
                Vthi[row * KSTR + c4 * 2 + 1] = h1;
                Vtlo[row * KSTR + c4 * 2]     = l0;
                Vtlo[row * KSTR + c4 * 2 + 1] = l1;
            }
        }
        __syncthreads();

        // S = Q K^T  (1-pass bf16; warp: 16 q-rows x 64 keys)
        float sacc[8][4];
#pragma unroll
        for (int i = 0; i < 8; ++i)
#pragma unroll
            for (int j = 0; j < 4; ++j) sacc[i][j] = 0.0f;
#pragma unroll
        for (int s = 0; s < 4; ++s) {
#pragma unroll
            for (int nt = 0; nt < 8; ++nt) {
                const int n0 = (nt * 8 + g) * KSTR + s * 8 + qd;
                mma_bf16(sacc[nt], qhf[s][0], qhf[s][1], qhf[s][2], qhf[s][3],
                         Khi[n0], Khi[n0 + 4]);
            }
        }

        // softcap + mask + exp in fragments, pack P hi/lo
        unsigned phi[8][2], plo[8][2];
#pragma unroll
        for (int nt = 0; nt < 8; ++nt) {
            float p[4];
#pragma unroll
            for (int e = 0; e < 4; ++e) {
                const int key = (c << 6) + nt * 8 + 2 * qd + (e & 1);
                const int qg  = (e < 2) ? qrow : (qrow + 8);
                const float sv  = sacc[nt][e];
                const float scx = sv * 0.125f;
                const float cap = scx - scx * scx * scx * (1.0f / 675.0f);
                const bool valid = (key <= qg) && ((key > qg - WINDOW) || (key < NGLOB));
                p[e] = valid ? __expf(cap) : 0.0f;
            }
            lsum0 += p[0] + p[1];
            lsum1 += p[2] + p[3];
            split2(p[0], p[1], phi[nt][0], plo[nt][0]);
            split2(p[2], p[3], phi[nt][1], plo[nt][1]);
        }

        // O += P V   (A-fragments = S C-fragments, FA2 identity; 3-pass)
#pragma unroll
        for (int s = 0; s < 4; ++s) {
            const unsigned a0h = phi[2 * s][0],     a1h = phi[2 * s][1];
            const unsigned a2h = phi[2 * s + 1][0], a3h = phi[2 * s + 1][1];
            const unsigned a0l = plo[2 * s][0],     a1l = plo[2 * s][1];
            const unsigned a2l = plo[2 * s + 1][0], a3l = plo[2 * s + 1][1];
#pragma unroll
            for (int nt = 0; nt < 8; ++nt) {
                const int n0 = (nt * 8 + g) * KSTR + s * 8 + qd;
                unsigned vb0 = Vthi[n0], vb1 = Vthi[n0 + 4];
                unsigned vl0 = Vtlo[n0], vl1 = Vtlo[n0 + 4];
                mma_bf16(oacc[nt], a0h, a1h, a2h, a3h, vb0, vb1);
                mma_bf16(oacc[nt], a0h, a1h, a2h, a3h, vl0, vl1);
                mma_bf16(oacc[nt], a0l, a1l, a2l, a3l, vb0, vb1);
            }
        }
        __syncthreads();
    }

    // reduce l across the 4 qd lanes (lane = 4*g + qd)
    lsum0 += __shfl_xor_sync(0xffffffffu, lsum0, 1);
    lsum0 += __shfl_xor_sync(0xffffffffu, lsum0, 2);
    lsum1 += __shfl_xor_sync(0xffffffffu, lsum1, 1);
    lsum1 += __shfl_xor_sync(0xffffffffu, lsum1, 2);
    const float i0 = 1.0f / lsum0;
    const float i1 = 1.0f / lsum1;

    float* Ob = g_ctx + ((size_t)(b * S_LEN + qrow) * NH + h) * DH;
#pragma unroll
    for (int nt = 0; nt < 8; ++nt) {
        float2 v0; v0.x = oacc[nt][0] * i0; v0.y = oacc[nt][1] * i0;
        float2 v1; v1.x = oacc[nt][2] * i1; v1.y = oacc[nt][3] * i1;
        *(float2*)(Ob + nt * 8 + 2 * qd) = v0;
        *(float2*)(Ob + 8 * NH * DH + nt * 8 + 2 * qd) = v1;   // row qrow+8
    }
}

// ---------------- launch ----------------
extern "C" void kernel_launch(void* const* d_in, const int* in_sizes, int n_in,
                              void* d_out, int out_size) {
    const float* x    = (const float*)d_in[0];
    const float* cosv = (const float*)d_in[1];
    const float* sinv = (const float*)d_in[2];
    // d_in[3] = mask (bool) — recomputed analytically
    const float* Wq   = (const float*)d_in[4];
    const float* Wk   = (const float*)d_in[5];
    const float* Wv   = (const float*)d_in[6];
    const float* Wo   = (const float*)d_in[7];
    float* out = (float*)d_out;

    tr_all_kernel<<<dim3(80, 32), dim3(32, 8)>>>(Wq, Wk, Wv, Wo);

    gemm_qkv_kernel<<<dim3(12, 32), 256>>>(x);

    const int nwarps  = BATCH * S_LEN * (NH + NKV);      // 81920
    const int nthread = nwarps * 32;
    normrope_kernel<<<(nthread + 255) / 256, 256>>>(cosv, sinv);

    attn_tc_kernel<<<dim3(S_LEN / 64, BATCH * NKV * 2), 256>>>();

    gemm_out_tf32_kernel<<<dim3(DMODEL / 128, (BATCH * S_LEN) / 128), 256>>>(out);
}